// round 6
// baseline (speedup 1.0000x reference)
#include <cuda_runtime.h>
#include <cuda_bf16.h>
#include <cstdint>
#include <cstddef>

#define HID        256
#define NNODES     50000
#define NEDGES     800000
#define NROWS_LBL  8192
#define SCAN_BLKS  196

// ---------------- scratch ----------------
__device__ float g_h [(size_t)NNODES * HID];
__device__ float g_x [(size_t)NNODES * HID];
__device__ __nv_bfloat16 g_xh[(size_t)NNODES * HID];
__device__ __nv_bfloat16 g_xl[(size_t)NNODES * HID];
__device__ __nv_bfloat16 g_wth[6 * 65536];
__device__ __nv_bfloat16 g_wtl[6 * 65536];
__device__ float g_beff[6 * 256];
__device__ int g_cnt[NNODES];
__device__ int g_off[NNODES + 1];
__device__ int g_eid[NEDGES];
__device__ int g_bsum[SCAN_BLKS];
__device__ int g_boff[SCAN_BLKS];

// ---------------- fused weight precompute ----------------
// Weff = A @ Wc ; stored transposed+split wth[m*65536 + n*256 + k]
__global__ __launch_bounds__(256)
void fuse_w(const float* __restrict__ f0w, const float* __restrict__ f1w,
            const float* __restrict__ cw,
            __nv_bfloat16* __restrict__ wth, __nv_bfloat16* __restrict__ wtl)
{
    __shared__ float sA[8][256];
    const int m = blockIdx.y;
    const int layer = m >> 1, which = m & 1;
    const float* A  = (which == 0 ? f0w : f1w) + (size_t)layer * 65536;
    const float* Wc = cw + (size_t)layer * 65536;
    const int k0 = blockIdx.x * 8;
    const int n  = threadIdx.x;

#pragma unroll
    for (int j = 0; j < 8; j++)
        sA[j][n] = A[(k0 + j) * 256 + n];
    __syncthreads();

    float acc[8];
#pragma unroll
    for (int j = 0; j < 8; j++) acc[j] = 0.f;

    for (int t = 0; t < 256; t++) {
        float wv = __ldg(&Wc[t * 256 + n]);
#pragma unroll
        for (int j = 0; j < 8; j++)
            acc[j] = fmaf(sA[j][t], wv, acc[j]);
    }
#pragma unroll
    for (int j = 0; j < 8; j++) {
        __nv_bfloat16 h = __float2bfloat16(acc[j]);
        __nv_bfloat16 l = __float2bfloat16(acc[j] - __bfloat162float(h));
        wth[(size_t)m * 65536 + n * 256 + k0 + j] = h;
        wtl[(size_t)m * 65536 + n * 256 + k0 + j] = l;
    }
}

__global__ __launch_bounds__(256)
void fuse_b(const float* __restrict__ f0b, const float* __restrict__ f1b,
            const float* __restrict__ cw, const float* __restrict__ cb,
            float* __restrict__ beff)
{
    __shared__ float sB[256];
    const int m = blockIdx.x;
    const int layer = m >> 1, which = m & 1;
    const float* b  = (which == 0 ? f0b : f1b) + (size_t)layer * 256;
    const float* Wc = cw + (size_t)layer * 65536;
    const int n = threadIdx.x;
    sB[n] = b[n];
    __syncthreads();
    float acc = __ldg(&cb[layer * 256 + n]);
#pragma unroll 8
    for (int t = 0; t < 256; t++)
        acc = fmaf(sB[t], __ldg(&Wc[t * 256 + n]), acc);
    beff[m * 256 + n] = acc;
}

// ---------------- mma.sync bf16 split GEMM, full N=256 per CTA ----------------
#define KC     32
#define LDSR   40                       // halves per row (80B) -> conflict-free
#define A_HB   (128 * LDSR * 2)         // 10240 B
#define B_HB   (256 * LDSR * 2)         // 20480 B
#define STG    (2 * A_HB + 2 * B_HB)    // 61440 B per stage

__device__ __forceinline__ void mma16816(float* c, const uint32_t* a, const uint32_t* b)
{
    asm volatile(
        "mma.sync.aligned.m16n8k16.row.col.f32.bf16.bf16.f32 "
        "{%0,%1,%2,%3}, {%4,%5,%6,%7}, {%8,%9}, {%0,%1,%2,%3};"
        : "+f"(c[0]), "+f"(c[1]), "+f"(c[2]), "+f"(c[3])
        : "r"(a[0]), "r"(a[1]), "r"(a[2]), "r"(a[3]), "r"(b[0]), "r"(b[1]));
}
__device__ __forceinline__ void cpa16(uint32_t dst, const void* src, int sz)
{
    asm volatile("cp.async.ca.shared.global [%0], [%1], 16, %2;"
                 :: "r"(dst), "l"(src), "r"(sz));
}
__device__ __forceinline__ void cpa_commit() { asm volatile("cp.async.commit_group;"); }
template <int N>
__device__ __forceinline__ void cpa_wait() {
    asm volatile("cp.async.wait_group %0;" :: "n"(N));
}

// 512 threads: 16 warps, 4x4 layout; warp tile 32(M) x 64(N); CTA 128 x 256.
__global__ __launch_bounds__(512, 1)
void tc_gemm(const __nv_bfloat16* __restrict__ Ah, const __nv_bfloat16* __restrict__ Al,
             const __nv_bfloat16* __restrict__ Wth, const __nv_bfloat16* __restrict__ Wtl,
             const float* __restrict__ bias, float* __restrict__ C,
             int M, const int* __restrict__ rowmap)
{
    extern __shared__ __align__(16) char smem_dyn[];

    const int tid  = threadIdx.x;
    const int wid  = tid >> 5;
    const int lane = tid & 31;
    const int bm   = blockIdx.x * 128;
    const int wr   = wid & 3;           // 4 m-strips of 32
    const int wc   = wid >> 2;          // 4 n-strips of 64
    const int qp   = lane >> 2;
    const int qr   = lane & 3;

    const uint32_t smem_u = (uint32_t)__cvta_generic_to_shared(smem_dyn);

    float acc[2][8][4];
#pragma unroll
    for (int i = 0; i < 2; i++)
#pragma unroll
        for (int j = 0; j < 8; j++)
#pragma unroll
            for (int r = 0; r < 4; r++) acc[i][j][r] = 0.f;

    // A row this thread stages (1 x 16B per matrix per stage)
    const int ar = tid >> 2;            // 0..127
    const int acq = tid & 3;
    int grow = bm + ar;
    const int arow = rowmap ? __ldg(&rowmap[grow]) : (grow < M ? grow : -1);

    auto load_stage = [&](int st, int k0) {
        const uint32_t sb = smem_u + st * STG;
        // A hi/lo
        {
            uint32_t doff = (uint32_t)(ar * (LDSR * 2) + acq * 16);
            int khalf = k0 + acq * 8;
            int sz = (arow >= 0) ? 16 : 0;
            size_t ro = (size_t)(arow >= 0 ? arow : 0) * HID + khalf;
            cpa16(sb + doff,        Ah + ro, sz);
            cpa16(sb + A_HB + doff, Al + ro, sz);
        }
        // B hi/lo: 256 rows x 4 quarters = 1024 ops / 512 threads
#pragma unroll
        for (int i = 0; i < 2; i++) {
            int u = i * 512 + tid;
            int r = u >> 2;
            int cq = u & 3;
            uint32_t doff = (uint32_t)(r * (LDSR * 2) + cq * 16);
            int khalf = k0 + cq * 8;
            cpa16(sb + 2 * A_HB + doff,        Wth + (size_t)r * HID + khalf, 16);
            cpa16(sb + 2 * A_HB + B_HB + doff, Wtl + (size_t)r * HID + khalf, 16);
        }
    };

    auto compute_stage = [&](int st) {
        const __nv_bfloat16* sAh = (const __nv_bfloat16*)(smem_dyn + st * STG);
        const __nv_bfloat16* sAl = (const __nv_bfloat16*)(smem_dyn + st * STG + A_HB);
        const __nv_bfloat16* sBh = (const __nv_bfloat16*)(smem_dyn + st * STG + 2 * A_HB);
        const __nv_bfloat16* sBl = (const __nv_bfloat16*)(smem_dyn + st * STG + 2 * A_HB + B_HB);
#pragma unroll
        for (int ks = 0; ks < KC; ks += 16) {
            const int kk = ks + qr * 2;
            uint32_t fAh[2][4], fAl[2][4];
#pragma unroll
            for (int mt = 0; mt < 2; mt++) {
                int r0 = wr * 32 + mt * 16 + qp;
                const __nv_bfloat16* ph = sAh + r0 * LDSR + kk;
                const __nv_bfloat16* pl = sAl + r0 * LDSR + kk;
                fAh[mt][0] = *(const uint32_t*)(ph);
                fAh[mt][1] = *(const uint32_t*)(ph + 8 * LDSR);
                fAh[mt][2] = *(const uint32_t*)(ph + 8);
                fAh[mt][3] = *(const uint32_t*)(ph + 8 * LDSR + 8);
                fAl[mt][0] = *(const uint32_t*)(pl);
                fAl[mt][1] = *(const uint32_t*)(pl + 8 * LDSR);
                fAl[mt][2] = *(const uint32_t*)(pl + 8);
                fAl[mt][3] = *(const uint32_t*)(pl + 8 * LDSR + 8);
            }
            // passes (Ah,Bh) + (Al,Bh)
#pragma unroll
            for (int ng = 0; ng < 2; ng++) {
                uint32_t fB[4][2];
#pragma unroll
                for (int j = 0; j < 4; j++) {
                    int n0 = wc * 64 + (ng * 4 + j) * 8 + qp;
                    const __nv_bfloat16* pb = sBh + n0 * LDSR + kk;
                    fB[j][0] = *(const uint32_t*)(pb);
                    fB[j][1] = *(const uint32_t*)(pb + 8);
                }
#pragma unroll
                for (int mt = 0; mt < 2; mt++)
#pragma unroll
                    for (int j = 0; j < 4; j++) {
                        mma16816(acc[mt][ng * 4 + j], fAh[mt], fB[j]);
                        mma16816(acc[mt][ng * 4 + j], fAl[mt], fB[j]);
                    }
            }
            // pass (Ah,Bl)
#pragma unroll
            for (int ng = 0; ng < 2; ng++) {
                uint32_t fB[4][2];
#pragma unroll
                for (int j = 0; j < 4; j++) {
                    int n0 = wc * 64 + (ng * 4 + j) * 8 + qp;
                    const __nv_bfloat16* pb = sBl + n0 * LDSR + kk;
                    fB[j][0] = *(const uint32_t*)(pb);
                    fB[j][1] = *(const uint32_t*)(pb + 8);
                }
#pragma unroll
                for (int mt = 0; mt < 2; mt++)
#pragma unroll
                    for (int j = 0; j < 4; j++)
                        mma16816(acc[mt][ng * 4 + j], fAh[mt], fB[j]);
            }
        }
    };

    load_stage(0, 0);
    cpa_commit();
#pragma unroll
    for (int c = 0; c < 8; c++) {
        if (c < 7) {
            load_stage((c + 1) & 1, (c + 1) * KC);
            cpa_commit();
            cpa_wait<1>();
        } else {
            cpa_wait<0>();
        }
        __syncthreads();
        compute_stage(c & 1);
        __syncthreads();
    }

    // epilogue
#pragma unroll
    for (int mt = 0; mt < 2; mt++) {
        int grow0 = bm + wr * 32 + mt * 16 + qp;
        int grow1 = grow0 + 8;
        int row0 = rowmap ? __ldg(&rowmap[grow0]) : grow0;
        int row1 = rowmap ? __ldg(&rowmap[grow1]) : grow1;
        bool v0 = rowmap ? true : (grow0 < M);
        bool v1 = rowmap ? true : (grow1 < M);
#pragma unroll
        for (int nt = 0; nt < 8; nt++) {
            int col = wc * 64 + nt * 8 + qr * 2;
            float b0 = __ldg(&bias[col]);
            float b1 = __ldg(&bias[col + 1]);
            if (v0) *(float2*)(C + (size_t)row0 * HID + col) =
                        make_float2(acc[mt][nt][0] + b0, acc[mt][nt][1] + b1);
            if (v1) *(float2*)(C + (size_t)row1 * HID + col) =
                        make_float2(acc[mt][nt][2] + b0, acc[mt][nt][3] + b1);
        }
    }
}

// ---------------- fp32 -> bf16 hi/lo pair (initial x only) ----------------
__global__ void to_pair(const float* __restrict__ in,
                        __nv_bfloat16* __restrict__ hi, __nv_bfloat16* __restrict__ lo,
                        int n4)
{
    int t = blockIdx.x * blockDim.x + threadIdx.x;
    if (t >= n4) return;
    float4 v = ((const float4*)in)[t];
    __nv_bfloat16 h0 = __float2bfloat16(v.x);
    __nv_bfloat16 h1 = __float2bfloat16(v.y);
    __nv_bfloat16 h2 = __float2bfloat16(v.z);
    __nv_bfloat16 h3 = __float2bfloat16(v.w);
    __nv_bfloat162 hp0(h0, h1), hp1(h2, h3);
    __nv_bfloat162 lp0(__float2bfloat16(v.x - __bfloat162float(h0)),
                       __float2bfloat16(v.y - __bfloat162float(h1)));
    __nv_bfloat162 lp1(__float2bfloat16(v.z - __bfloat162float(h2)),
                       __float2bfloat16(v.w - __bfloat162float(h3)));
    ((__nv_bfloat162*)hi)[t * 2 + 0] = hp0;
    ((__nv_bfloat162*)hi)[t * 2 + 1] = hp1;
    ((__nv_bfloat162*)lo)[t * 2 + 0] = lp0;
    ((__nv_bfloat162*)lo)[t * 2 + 1] = lp1;
}

// ---------------- CSR build ----------------
__global__ void csr_zero(int* __restrict__ cnt)
{
    int t = blockIdx.x * blockDim.x + threadIdx.x;
    if (t < NNODES) cnt[t] = 0;
}
__global__ void csr_hist(const int* __restrict__ dst, int* __restrict__ cnt)
{
    int t = blockIdx.x * blockDim.x + threadIdx.x;
    if (t < NEDGES) atomicAdd(&cnt[__ldg(&dst[t])], 1);
}
__global__ __launch_bounds__(256)
void scan_blk(const int* __restrict__ cnt, int* __restrict__ off, int* __restrict__ bsum)
{
    __shared__ int sh[256];
    int idx = blockIdx.x * 256 + threadIdx.x;
    int v = (idx < NNODES) ? cnt[idx] : 0;
    sh[threadIdx.x] = v;
    __syncthreads();
#pragma unroll
    for (int d = 1; d < 256; d <<= 1) {
        int t = (threadIdx.x >= d) ? sh[threadIdx.x - d] : 0;
        __syncthreads();
        sh[threadIdx.x] += t;
        __syncthreads();
    }
    if (idx < NNODES) off[idx] = sh[threadIdx.x] - v;
    if (threadIdx.x == 255) bsum[blockIdx.x] = sh[255];
}
__global__ __launch_bounds__(256)
void scan_top(const int* __restrict__ bsum, int* __restrict__ boff)
{
    __shared__ int sh[256];
    int v = (threadIdx.x < SCAN_BLKS) ? bsum[threadIdx.x] : 0;
    sh[threadIdx.x] = v;
    __syncthreads();
#pragma unroll
    for (int d = 1; d < 256; d <<= 1) {
        int t = (threadIdx.x >= d) ? sh[threadIdx.x - d] : 0;
        __syncthreads();
        sh[threadIdx.x] += t;
        __syncthreads();
    }
    if (threadIdx.x < SCAN_BLKS) boff[threadIdx.x] = sh[threadIdx.x] - v;
}
__global__ void scan_add(int* __restrict__ off, const int* __restrict__ boff,
                         int* __restrict__ cnt)
{
    int idx = blockIdx.x * 256 + threadIdx.x;
    if (idx < NNODES) {
        off[idx] += boff[blockIdx.x];
        cnt[idx] = 0;
    }
    if (idx == 0) off[NNODES] = NEDGES;
}
__global__ void csr_fill(const int* __restrict__ src, const int* __restrict__ dst,
                         const int* __restrict__ off, int* __restrict__ cur,
                         int* __restrict__ eid)
{
    int t = blockIdx.x * blockDim.x + threadIdx.x;
    if (t >= NEDGES) return;
    int d = __ldg(&dst[t]);
    int p = atomicAdd(&cur[d], 1);
    eid[__ldg(&off[d]) + p] = __ldg(&src[t]);
}

// ---------------- pull segment-sum (+ optional fused outputs) ----------------
__global__ __launch_bounds__(256)
void pull_sum(const float* __restrict__ h, const int* __restrict__ off,
              const int* __restrict__ eid, float* __restrict__ xc,
              __nv_bfloat16* __restrict__ xh, __nv_bfloat16* __restrict__ xl,
              int wf32, int wpair)
{
    int node = blockIdx.x * 8 + (threadIdx.x >> 5);
    if (node >= NNODES) return;
    int lane = threadIdx.x & 31;
    int s0 = __ldg(&off[node]);
    int s1 = __ldg(&off[node + 1]);
    float4 a0 = make_float4(0.f, 0.f, 0.f, 0.f), a1 = a0;
    const float4* H = (const float4*)h;
    int i = s0;
    for (; i + 1 < s1; i += 2) {
        int e0 = __ldg(&eid[i]);
        int e1 = __ldg(&eid[i + 1]);
        const float4* r0 = H + (size_t)e0 * 64 + lane * 2;
        const float4* r1 = H + (size_t)e1 * 64 + lane * 2;
        float4 v00 = __ldg(r0), v01 = __ldg(r0 + 1);
        float4 v10 = __ldg(r1), v11 = __ldg(r1 + 1);
        a0.x += v00.x; a0.y += v00.y; a0.z += v00.z; a0.w += v00.w;
        a1.x += v01.x; a1.y += v01.y; a1.z += v01.z; a1.w += v01.w;
        a0.x += v10.x; a0.y += v10.y; a0.z += v10.z; a0.w += v10.w;
        a1.x += v11.x; a1.y += v11.y; a1.z += v11.z; a1.w += v11.w;
    }
    if (i < s1) {
        int e0 = __ldg(&eid[i]);
        const float4* r0 = H + (size_t)e0 * 64 + lane * 2;
        float4 v00 = __ldg(r0), v01 = __ldg(r0 + 1);
        a0.x += v00.x; a0.y += v00.y; a0.z += v00.z; a0.w += v00.w;
        a1.x += v01.x; a1.y += v01.y; a1.z += v01.z; a1.w += v01.w;
    }
    if (wf32) {
        float4* X = (float4*)xc + (size_t)node * 64 + lane * 2;
        X[0] = a0; X[1] = a1;
    }
    if (wpair) {
        float vals[8] = {a0.x, a0.y, a0.z, a0.w, a1.x, a1.y, a1.z, a1.w};
        __nv_bfloat16 hv[8], lv[8];
#pragma unroll
        for (int j = 0; j < 8; j++) {
            hv[j] = __float2bfloat16(vals[j]);
            lv[j] = __float2bfloat16(vals[j] - __bfloat162float(hv[j]));
        }
        *(uint4*)(xh + (size_t)node * HID + lane * 8) = *(uint4*)hv;
        *(uint4*)(xl + (size_t)node * HID + lane * 8) = *(uint4*)lv;
    }
}

__global__ void gather_out(const float* __restrict__ x, const int* __restrict__ pos,
                           float4* __restrict__ out)
{
    int t = blockIdx.x * blockDim.x + threadIdx.x;
    if (t >= NROWS_LBL * 64) return;
    int r = t >> 6, c = t & 63;
    int row = __ldg(&pos[r]);
    out[t] = *(const float4*)(x + (size_t)row * HID + (c << 2));
}

// ---------------- launch ----------------
extern "C" void kernel_launch(void* const* d_in, const int* in_sizes, int n_in,
                              void* d_out, int out_size)
{
    (void)in_sizes; (void)n_in; (void)out_size;
    const float* x    = (const float*)d_in[0];
    const float* f0w  = (const float*)d_in[1];
    const float* f0b  = (const float*)d_in[2];
    const float* f1w  = (const float*)d_in[3];
    const float* f1b  = (const float*)d_in[4];
    const float* cw   = (const float*)d_in[5];
    const float* cb   = (const float*)d_in[6];
    const int*   esrc = (const int*)d_in[7];
    const int*   edst = (const int*)d_in[8];
    const int*   pos  = (const int*)d_in[9];

    float *h, *xc, *beff;
    __nv_bfloat16 *xh, *xl, *wth, *wtl;
    int *cnt, *off, *eid, *bsum, *boff;
    cudaGetSymbolAddress((void**)&h,    g_h);
    cudaGetSymbolAddress((void**)&xc,   g_x);
    cudaGetSymbolAddress((void**)&xh,   g_xh);
    cudaGetSymbolAddress((void**)&xl,   g_xl);
    cudaGetSymbolAddress((void**)&wth,  g_wth);
    cudaGetSymbolAddress((void**)&wtl,  g_wtl);
    cudaGetSymbolAddress((void**)&beff, g_beff);
    cudaGetSymbolAddress((void**)&cnt,  g_cnt);
    cudaGetSymbolAddress((void**)&off,  g_off);
    cudaGetSymbolAddress((void**)&eid,  g_eid);
    cudaGetSymbolAddress((void**)&bsum, g_bsum);
    cudaGetSymbolAddress((void**)&boff, g_boff);

    const int SMEM_DYN = 2 * STG;   // 122880
    cudaFuncSetAttribute(tc_gemm, cudaFuncAttributeMaxDynamicSharedMemorySize, SMEM_DYN);

    const int n4 = NNODES * HID / 4;
    const int gN = (NNODES + 127) / 128;   // 391
    const int gL = NROWS_LBL / 128;        // 64

    fuse_w<<<dim3(32, 6), 256>>>(f0w, f1w, cw, wth, wtl);
    fuse_b<<<6, 256>>>(f0b, f1b, cw, cb, beff);
    csr_zero<<<(NNODES + 255) / 256, 256>>>(cnt);
    csr_hist<<<(NEDGES + 255) / 256, 256>>>(edst, cnt);
    scan_blk<<<SCAN_BLKS, 256>>>(cnt, off, bsum);
    scan_top<<<1, 256>>>(bsum, boff);
    scan_add<<<SCAN_BLKS, 256>>>(off, boff, cnt);
    csr_fill<<<(NEDGES + 255) / 256, 256>>>(esrc, edst, off, cnt, eid);

    to_pair<<<(n4 + 255) / 256, 256>>>(x, xh, xl, n4);

    for (int i = 0; i < 3; i++) {
        const size_t wo0 = (size_t)(i * 2 + 0) * 65536;
        const size_t wo1 = (size_t)(i * 2 + 1) * 65536;
        tc_gemm<<<gN, 512, SMEM_DYN>>>(xh, xl, wth + wo0, wtl + wo0,
                                       beff + (i * 2 + 0) * 256, h, NNODES, nullptr);
        tc_gemm<<<gL, 512, SMEM_DYN>>>(xh, xl, wth + wo1, wtl + wo1,
                                       beff + (i * 2 + 1) * 256, h, NROWS_LBL, pos);
        int last = (i == 2);
        pull_sum<<<(NNODES + 7) / 8, 256>>>(h, off, eid, xc, xh, xl,
                                            last ? 1 : 0, last ? 0 : 1);
    }
    gather_out<<<(NROWS_LBL * 64 + 255) / 256, 256>>>(xc, pos, (float4*)d_out);
}

// round 7
// speedup vs baseline: 1.0751x; 1.0751x over previous
#include <cuda_runtime.h>
#include <cuda_bf16.h>
#include <cstdint>
#include <cstddef>

#define HID        256
#define NNODES     50000
#define NEDGES     800000
#define NROWS_LBL  8192
#define SCAN_BLKS  196

// ---------------- scratch ----------------
__device__ float g_h [(size_t)NNODES * HID];
__device__ float g_x [(size_t)NNODES * HID];
__device__ __nv_bfloat16 g_xh[(size_t)NNODES * HID];
__device__ __nv_bfloat16 g_xl[(size_t)NNODES * HID];
__device__ __nv_bfloat16 g_wth[6 * 65536];
__device__ __nv_bfloat16 g_wtl[6 * 65536];
__device__ float g_beff[6 * 256];
__device__ int g_cnt[NNODES];
__device__ int g_off[NNODES + 1];
__device__ int g_eid[NEDGES];
__device__ int g_bsum[SCAN_BLKS];
__device__ int g_boff[SCAN_BLKS];

// ---------------- fused weight precompute (retiled) ----------------
__global__ __launch_bounds__(256)
void fuse_w(const float* __restrict__ f0w, const float* __restrict__ f1w,
            const float* __restrict__ cw,
            __nv_bfloat16* __restrict__ wth, __nv_bfloat16* __restrict__ wtl)
{
    __shared__ float sA[8][256];
    const int m = blockIdx.y;
    const int layer = m >> 1, which = m & 1;
    const float* A  = (which == 0 ? f0w : f1w) + (size_t)layer * 65536;
    const float* Wc = cw + (size_t)layer * 65536;
    const int k0 = blockIdx.x * 8;
    const int n  = threadIdx.x;

#pragma unroll
    for (int j = 0; j < 8; j++)
        sA[j][n] = A[(k0 + j) * 256 + n];
    __syncthreads();

    float acc[8];
#pragma unroll
    for (int j = 0; j < 8; j++) acc[j] = 0.f;

    for (int t = 0; t < 256; t++) {
        float wv = __ldg(&Wc[t * 256 + n]);
#pragma unroll
        for (int j = 0; j < 8; j++)
            acc[j] = fmaf(sA[j][t], wv, acc[j]);
    }
#pragma unroll
    for (int j = 0; j < 8; j++) {
        __nv_bfloat16 h = __float2bfloat16(acc[j]);
        __nv_bfloat16 l = __float2bfloat16(acc[j] - __bfloat162float(h));
        wth[(size_t)m * 65536 + n * 256 + k0 + j] = h;
        wtl[(size_t)m * 65536 + n * 256 + k0 + j] = l;
    }
}

__global__ __launch_bounds__(256)
void fuse_b(const float* __restrict__ f0b, const float* __restrict__ f1b,
            const float* __restrict__ cw, const float* __restrict__ cb,
            float* __restrict__ beff)
{
    __shared__ float sB[256];
    const int m = blockIdx.x;
    const int layer = m >> 1, which = m & 1;
    const float* b  = (which == 0 ? f0b : f1b) + (size_t)layer * 256;
    const float* Wc = cw + (size_t)layer * 65536;
    const int n = threadIdx.x;
    sB[n] = b[n];
    __syncthreads();
    float acc = __ldg(&cb[layer * 256 + n]);
#pragma unroll 8
    for (int t = 0; t < 256; t++)
        acc = fmaf(sB[t], __ldg(&Wc[t * 256 + n]), acc);
    beff[m * 256 + n] = acc;
}

// ---------------- mma.sync bf16 split GEMM (R5 geometry: 128x128, 256 thr) ----------------
#define KC      32
#define LDS_A   40
#define TILE_HB (128 * LDS_A * 2)   // 10240
#define STAGE_B (4 * TILE_HB)       // 40960

__device__ __forceinline__ void mma16816(float* c, const uint32_t* a, const uint32_t* b)
{
    asm volatile(
        "mma.sync.aligned.m16n8k16.row.col.f32.bf16.bf16.f32 "
        "{%0,%1,%2,%3}, {%4,%5,%6,%7}, {%8,%9}, {%0,%1,%2,%3};"
        : "+f"(c[0]), "+f"(c[1]), "+f"(c[2]), "+f"(c[3])
        : "r"(a[0]), "r"(a[1]), "r"(a[2]), "r"(a[3]), "r"(b[0]), "r"(b[1]));
}
__device__ __forceinline__ void cpa16(uint32_t dst, const void* src, int sz)
{
    asm volatile("cp.async.ca.shared.global [%0], [%1], 16, %2;"
                 :: "r"(dst), "l"(src), "r"(sz));
}
__device__ __forceinline__ void cpa_commit() { asm volatile("cp.async.commit_group;"); }
template <int N>
__device__ __forceinline__ void cpa_wait() {
    asm volatile("cp.async.wait_group %0;" :: "n"(N));
}

__global__ __launch_bounds__(256, 2)
void tc_gemm(const __nv_bfloat16* __restrict__ Ah, const __nv_bfloat16* __restrict__ Al,
             const __nv_bfloat16* __restrict__ Wth, const __nv_bfloat16* __restrict__ Wtl,
             const float* __restrict__ bias, float* __restrict__ C,
             int M, const int* __restrict__ rowmap)
{
    extern __shared__ __align__(16) char smem_dyn[];

    const int tid  = threadIdx.x;
    const int wid  = tid >> 5;
    const int lane = tid & 31;
    const int bm   = blockIdx.x * 128;
    const int bn   = blockIdx.y * 128;
    const int wr   = wid & 1;
    const int wc   = wid >> 1;
    const int qp = lane >> 2;
    const int qr = lane & 3;

    const uint32_t smem_u = (uint32_t)__cvta_generic_to_shared(smem_dyn);

    float acc[4][4][4];
#pragma unroll
    for (int i = 0; i < 4; i++)
#pragma unroll
        for (int j = 0; j < 4; j++)
#pragma unroll
            for (int r = 0; r < 4; r++) acc[i][j][r] = 0.f;

    int arow[2];
#pragma unroll
    for (int i = 0; i < 2; i++) {
        int u = i * 256 + tid;
        int r = u >> 2;
        int grow = bm + r;
        arow[i] = rowmap ? __ldg(&rowmap[grow]) : (grow < M ? grow : -1);
    }

    auto load_stage = [&](int st, int k0) {
        const uint32_t sb = smem_u + st * STAGE_B;
#pragma unroll
        for (int i = 0; i < 2; i++) {
            int u = i * 256 + tid;
            int r = u >> 2;
            int cq = (u & 3);
            uint32_t doff = (uint32_t)(r * (LDS_A * 2) + cq * 16);
            int khalf = k0 + cq * 8;
            int sz = (arow[i] >= 0) ? 16 : 0;
            const __nv_bfloat16* gh = Ah + ((size_t)(arow[i] >= 0 ? arow[i] : 0)) * HID + khalf;
            const __nv_bfloat16* gl = Al + ((size_t)(arow[i] >= 0 ? arow[i] : 0)) * HID + khalf;
            cpa16(sb + 0 * TILE_HB + doff, gh, sz);
            cpa16(sb + 1 * TILE_HB + doff, gl, sz);
            cpa16(sb + 2 * TILE_HB + doff, Wth + (size_t)(bn + r) * HID + khalf, 16);
            cpa16(sb + 3 * TILE_HB + doff, Wtl + (size_t)(bn + r) * HID + khalf, 16);
        }
    };

    auto compute_stage = [&](int st) {
        const __nv_bfloat16* sAh = (const __nv_bfloat16*)(smem_dyn + st * STAGE_B + 0 * TILE_HB);
        const __nv_bfloat16* sAl = (const __nv_bfloat16*)(smem_dyn + st * STAGE_B + 1 * TILE_HB);
        const __nv_bfloat16* sBh = (const __nv_bfloat16*)(smem_dyn + st * STAGE_B + 2 * TILE_HB);
        const __nv_bfloat16* sBl = (const __nv_bfloat16*)(smem_dyn + st * STAGE_B + 3 * TILE_HB);
#pragma unroll
        for (int ks = 0; ks < KC; ks += 16) {
            uint32_t fAh[4][4], fAl[4][4];
#pragma unroll
            for (int mt = 0; mt < 4; mt++) {
                int r0 = wr * 64 + mt * 16 + qp;
                int kk = ks + qr * 2;
                const __nv_bfloat16* ph = sAh + r0 * LDS_A + kk;
                const __nv_bfloat16* pl = sAl + r0 * LDS_A + kk;
                fAh[mt][0] = *(const uint32_t*)(ph);
                fAh[mt][1] = *(const uint32_t*)(ph + 8 * LDS_A);
                fAh[mt][2] = *(const uint32_t*)(ph + 8);
                fAh[mt][3] = *(const uint32_t*)(ph + 8 * LDS_A + 8);
                fAl[mt][0] = *(const uint32_t*)(pl);
                fAl[mt][1] = *(const uint32_t*)(pl + 8 * LDS_A);
                fAl[mt][2] = *(const uint32_t*)(pl + 8);
                fAl[mt][3] = *(const uint32_t*)(pl + 8 * LDS_A + 8);
            }
            {
                uint32_t fB[4][2];
#pragma unroll
                for (int nt = 0; nt < 4; nt++) {
                    int n0 = wc * 32 + nt * 8 + qp;
                    int kk = ks + qr * 2;
                    const __nv_bfloat16* pb = sBh + n0 * LDS_A + kk;
                    fB[nt][0] = *(const uint32_t*)(pb);
                    fB[nt][1] = *(const uint32_t*)(pb + 8);
                }
#pragma unroll
                for (int mt = 0; mt < 4; mt++)
#pragma unroll
                    for (int nt = 0; nt < 4; nt++) {
                        mma16816(acc[mt][nt], fAh[mt], fB[nt]);
                        mma16816(acc[mt][nt], fAl[mt], fB[nt]);
                    }
            }
            {
                uint32_t fB[4][2];
#pragma unroll
                for (int nt = 0; nt < 4; nt++) {
                    int n0 = wc * 32 + nt * 8 + qp;
                    int kk = ks + qr * 2;
                    const __nv_bfloat16* pb = sBl + n0 * LDS_A + kk;
                    fB[nt][0] = *(const uint32_t*)(pb);
                    fB[nt][1] = *(const uint32_t*)(pb + 8);
                }
#pragma unroll
                for (int mt = 0; mt < 4; mt++)
#pragma unroll
                    for (int nt = 0; nt < 4; nt++)
                        mma16816(acc[mt][nt], fAh[mt], fB[nt]);
            }
        }
    };

    load_stage(0, 0);
    cpa_commit();
#pragma unroll
    for (int c = 0; c < 8; c++) {
        if (c < 7) {
            load_stage((c + 1) & 1, (c + 1) * KC);
            cpa_commit();
            cpa_wait<1>();
        } else {
            cpa_wait<0>();
        }
        __syncthreads();
        compute_stage(c & 1);
        __syncthreads();
    }

#pragma unroll
    for (int mt = 0; mt < 4; mt++) {
        int grow0 = bm + wr * 64 + mt * 16 + qp;
        int grow1 = grow0 + 8;
        int row0 = rowmap ? __ldg(&rowmap[grow0]) : grow0;
        int row1 = rowmap ? __ldg(&rowmap[grow1]) : grow1;
        bool v0 = rowmap ? true : (grow0 < M);
        bool v1 = rowmap ? true : (grow1 < M);
#pragma unroll
        for (int nt = 0; nt < 4; nt++) {
            int col = bn + wc * 32 + nt * 8 + qr * 2;
            float b0 = __ldg(&bias[col]);
            float b1 = __ldg(&bias[col + 1]);
            if (v0) *(float2*)(C + (size_t)row0 * HID + col) =
                        make_float2(acc[mt][nt][0] + b0, acc[mt][nt][1] + b1);
            if (v1) *(float2*)(C + (size_t)row1 * HID + col) =
                        make_float2(acc[mt][nt][2] + b0, acc[mt][nt][3] + b1);
        }
    }
}

// ---------------- fp32 -> bf16 hi/lo pair (initial x only) ----------------
__global__ void to_pair(const float* __restrict__ in,
                        __nv_bfloat16* __restrict__ hi, __nv_bfloat16* __restrict__ lo,
                        int n4)
{
    int t = blockIdx.x * blockDim.x + threadIdx.x;
    if (t >= n4) return;
    float4 v = ((const float4*)in)[t];
    __nv_bfloat16 h0 = __float2bfloat16(v.x);
    __nv_bfloat16 h1 = __float2bfloat16(v.y);
    __nv_bfloat16 h2 = __float2bfloat16(v.z);
    __nv_bfloat16 h3 = __float2bfloat16(v.w);
    __nv_bfloat162 hp0(h0, h1), hp1(h2, h3);
    __nv_bfloat162 lp0(__float2bfloat16(v.x - __bfloat162float(h0)),
                       __float2bfloat16(v.y - __bfloat162float(h1)));
    __nv_bfloat162 lp1(__float2bfloat16(v.z - __bfloat162float(h2)),
                       __float2bfloat16(v.w - __bfloat162float(h3)));
    ((__nv_bfloat162*)hi)[t * 2 + 0] = hp0;
    ((__nv_bfloat162*)hi)[t * 2 + 1] = hp1;
    ((__nv_bfloat162*)lo)[t * 2 + 0] = lp0;
    ((__nv_bfloat162*)lo)[t * 2 + 1] = lp1;
}

// ---------------- CSR build ----------------
__global__ void csr_zero(int* __restrict__ cnt)
{
    int t = blockIdx.x * blockDim.x + threadIdx.x;
    if (t < NNODES) cnt[t] = 0;
}
__global__ void csr_hist(const int* __restrict__ dst, int* __restrict__ cnt)
{
    int t = blockIdx.x * blockDim.x + threadIdx.x;
    if (t < NEDGES) atomicAdd(&cnt[__ldg(&dst[t])], 1);
}
__global__ __launch_bounds__(256)
void scan_blk(const int* __restrict__ cnt, int* __restrict__ off, int* __restrict__ bsum)
{
    __shared__ int sh[256];
    int idx = blockIdx.x * 256 + threadIdx.x;
    int v = (idx < NNODES) ? cnt[idx] : 0;
    sh[threadIdx.x] = v;
    __syncthreads();
#pragma unroll
    for (int d = 1; d < 256; d <<= 1) {
        int t = (threadIdx.x >= d) ? sh[threadIdx.x - d] : 0;
        __syncthreads();
        sh[threadIdx.x] += t;
        __syncthreads();
    }
    if (idx < NNODES) off[idx] = sh[threadIdx.x] - v;
    if (threadIdx.x == 255) bsum[blockIdx.x] = sh[255];
}
__global__ __launch_bounds__(256)
void scan_top(const int* __restrict__ bsum, int* __restrict__ boff)
{
    __shared__ int sh[256];
    int v = (threadIdx.x < SCAN_BLKS) ? bsum[threadIdx.x] : 0;
    sh[threadIdx.x] = v;
    __syncthreads();
#pragma unroll
    for (int d = 1; d < 256; d <<= 1) {
        int t = (threadIdx.x >= d) ? sh[threadIdx.x - d] : 0;
        __syncthreads();
        sh[threadIdx.x] += t;
        __syncthreads();
    }
    if (threadIdx.x < SCAN_BLKS) boff[threadIdx.x] = sh[threadIdx.x] - v;
}
__global__ void scan_add(int* __restrict__ off, const int* __restrict__ boff,
                         int* __restrict__ cnt)
{
    int idx = blockIdx.x * 256 + threadIdx.x;
    if (idx < NNODES) {
        off[idx] += boff[blockIdx.x];
        cnt[idx] = 0;
    }
    if (idx == 0) off[NNODES] = NEDGES;
}
__global__ void csr_fill(const int* __restrict__ src, const int* __restrict__ dst,
                         const int* __restrict__ off, int* __restrict__ cur,
                         int* __restrict__ eid)
{
    int t = blockIdx.x * blockDim.x + threadIdx.x;
    if (t >= NEDGES) return;
    int d = __ldg(&dst[t]);
    int p = atomicAdd(&cur[d], 1);
    eid[__ldg(&off[d]) + p] = __ldg(&src[t]);
}

// ---------------- pull segment-sum (+ optional fused outputs) ----------------
__global__ __launch_bounds__(256)
void pull_sum(const float* __restrict__ h, const int* __restrict__ off,
              const int* __restrict__ eid, float* __restrict__ xc,
              __nv_bfloat16* __restrict__ xh, __nv_bfloat16* __restrict__ xl,
              int wf32, int wpair)
{
    int node = blockIdx.x * 8 + (threadIdx.x >> 5);
    if (node >= NNODES) return;
    int lane = threadIdx.x & 31;
    int s0 = __ldg(&off[node]);
    int s1 = __ldg(&off[node + 1]);
    float4 a0 = make_float4(0.f, 0.f, 0.f, 0.f), a1 = a0;
    const float4* H = (const float4*)h;
    int i = s0;
    for (; i + 1 < s1; i += 2) {
        int e0 = __ldg(&eid[i]);
        int e1 = __ldg(&eid[i + 1]);
        const float4* r0 = H + (size_t)e0 * 64 + lane * 2;
        const float4* r1 = H + (size_t)e1 * 64 + lane * 2;
        float4 v00 = __ldg(r0), v01 = __ldg(r0 + 1);
        float4 v10 = __ldg(r1), v11 = __ldg(r1 + 1);
        a0.x += v00.x; a0.y += v00.y; a0.z += v00.z; a0.w += v00.w;
        a1.x += v01.x; a1.y += v01.y; a1.z += v01.z; a1.w += v01.w;
        a0.x += v10.x; a0.y += v10.y; a0.z += v10.z; a0.w += v10.w;
        a1.x += v11.x; a1.y += v11.y; a1.z += v11.z; a1.w += v11.w;
    }
    if (i < s1) {
        int e0 = __ldg(&eid[i]);
        const float4* r0 = H + (size_t)e0 * 64 + lane * 2;
        float4 v00 = __ldg(r0), v01 = __ldg(r0 + 1);
        a0.x += v00.x; a0.y += v00.y; a0.z += v00.z; a0.w += v00.w;
        a1.x += v01.x; a1.y += v01.y; a1.z += v01.z; a1.w += v01.w;
    }
    if (wf32) {
        float4* X = (float4*)xc + (size_t)node * 64 + lane * 2;
        X[0] = a0; X[1] = a1;
    }
    if (wpair) {
        float vals[8] = {a0.x, a0.y, a0.z, a0.w, a1.x, a1.y, a1.z, a1.w};
        __nv_bfloat16 hv[8], lv[8];
#pragma unroll
        for (int j = 0; j < 8; j++) {
            hv[j] = __float2bfloat16(vals[j]);
            lv[j] = __float2bfloat16(vals[j] - __bfloat162float(hv[j]));
        }
        *(uint4*)(xh + (size_t)node * HID + lane * 8) = *(uint4*)hv;
        *(uint4*)(xl + (size_t)node * HID + lane * 8) = *(uint4*)lv;
    }
}

__global__ void gather_out(const float* __restrict__ x, const int* __restrict__ pos,
                           float4* __restrict__ out)
{
    int t = blockIdx.x * blockDim.x + threadIdx.x;
    if (t >= NROWS_LBL * 64) return;
    int r = t >> 6, c = t & 63;
    int row = __ldg(&pos[r]);
    out[t] = *(const float4*)(x + (size_t)row * HID + (c << 2));
}

// ---------------- launch ----------------
extern "C" void kernel_launch(void* const* d_in, const int* in_sizes, int n_in,
                              void* d_out, int out_size)
{
    (void)in_sizes; (void)n_in; (void)out_size;
    const float* x    = (const float*)d_in[0];
    const float* f0w  = (const float*)d_in[1];
    const float* f0b  = (const float*)d_in[2];
    const float* f1w  = (const float*)d_in[3];
    const float* f1b  = (const float*)d_in[4];
    const float* cw   = (const float*)d_in[5];
    const float* cb   = (const float*)d_in[6];
    const int*   esrc = (const int*)d_in[7];
    const int*   edst = (const int*)d_in[8];
    const int*   pos  = (const int*)d_in[9];

    float *h, *xc, *beff;
    __nv_bfloat16 *xh, *xl, *wth, *wtl;
    int *cnt, *off, *eid, *bsum, *boff;
    cudaGetSymbolAddress((void**)&h,    g_h);
    cudaGetSymbolAddress((void**)&xc,   g_x);
    cudaGetSymbolAddress((void**)&xh,   g_xh);
    cudaGetSymbolAddress((void**)&xl,   g_xl);
    cudaGetSymbolAddress((void**)&wth,  g_wth);
    cudaGetSymbolAddress((void**)&wtl,  g_wtl);
    cudaGetSymbolAddress((void**)&beff, g_beff);
    cudaGetSymbolAddress((void**)&cnt,  g_cnt);
    cudaGetSymbolAddress((void**)&off,  g_off);
    cudaGetSymbolAddress((void**)&eid,  g_eid);
    cudaGetSymbolAddress((void**)&bsum, g_bsum);
    cudaGetSymbolAddress((void**)&boff, g_boff);

    const int SMEM_DYN = 2 * STAGE_B;   // 81920
    cudaFuncSetAttribute(tc_gemm, cudaFuncAttributeMaxDynamicSharedMemorySize, SMEM_DYN);

    const int n4 = NNODES * HID / 4;
    dim3 gN((NNODES + 127) / 128, 2);
    dim3 gL(NROWS_LBL / 128, 2);

    fuse_w<<<dim3(32, 6), 256>>>(f0w, f1w, cw, wth, wtl);
    fuse_b<<<6, 256>>>(f0b, f1b, cw, cb, beff);
    csr_zero<<<(NNODES + 255) / 256, 256>>>(cnt);
    csr_hist<<<(NEDGES + 255) / 256, 256>>>(edst, cnt);
    scan_blk<<<SCAN_BLKS, 256>>>(cnt, off, bsum);
    scan_top<<<1, 256>>>(bsum, boff);
    scan_add<<<SCAN_BLKS, 256>>>(off, boff, cnt);
    csr_fill<<<(NEDGES + 255) / 256, 256>>>(esrc, edst, off, cnt, eid);

    to_pair<<<(n4 + 255) / 256, 256>>>(x, xh, xl, n4);

    for (int i = 0; i < 3; i++) {
        const size_t wo0 = (size_t)(i * 2 + 0) * 65536;
        const size_t wo1 = (size_t)(i * 2 + 1) * 65536;
        tc_gemm<<<gN, 256, SMEM_DYN>>>(xh, xl, wth + wo0, wtl + wo0,
                                       beff + (i * 2 + 0) * 256, h, NNODES, nullptr);
        tc_gemm<<<gL, 256, SMEM_DYN>>>(xh, xl, wth + wo1, wtl + wo1,
                                       beff + (i * 2 + 1) * 256, h, NROWS_LBL, pos);
        int last = (i == 2);
        pull_sum<<<(NNODES + 7) / 8, 256>>>(h, off, eid, xc, xh, xl,
                                            last ? 1 : 0, last ? 0 : 1);
    }
    gather_out<<<(NROWS_LBL * 64 + 255) / 256, 256>>>(xc, pos, (float4*)d_out);
}

// round 8
// speedup vs baseline: 1.1280x; 1.0492x over previous
#include <cuda_runtime.h>
#include <cuda_bf16.h>
#include <cstdint>
#include <cstddef>

#define HID        256
#define NNODES     50000
#define NEDGES     800000
#define NROWS_LBL  8192
#define SCAN_BLKS  196

// ---------------- scratch ----------------
__device__ float g_h [(size_t)NNODES * HID];
__device__ float g_x [(size_t)NNODES * HID];
__device__ __nv_bfloat16 g_xh[(size_t)NNODES * HID];
__device__ __nv_bfloat16 g_xl[(size_t)NNODES * HID];
__device__ __nv_bfloat16 g_wth[6 * 65536];
__device__ __nv_bfloat16 g_wtl[6 * 65536];
__device__ float g_beff[6 * 256];
__device__ int g_cnt[NNODES];
__device__ int g_off[NNODES + 1];
__device__ int g_eid[NEDGES];
__device__ int g_bsum[SCAN_BLKS];
__device__ int g_boff[SCAN_BLKS];

// ---------------- fused weight precompute ----------------
__global__ __launch_bounds__(256)
void fuse_w(const float* __restrict__ f0w, const float* __restrict__ f1w,
            const float* __restrict__ cw,
            __nv_bfloat16* __restrict__ wth, __nv_bfloat16* __restrict__ wtl)
{
    __shared__ float sA[8][256];
    const int m = blockIdx.y;
    const int layer = m >> 1, which = m & 1;
    const float* A  = (which == 0 ? f0w : f1w) + (size_t)layer * 65536;
    const float* Wc = cw + (size_t)layer * 65536;
    const int k0 = blockIdx.x * 8;
    const int n  = threadIdx.x;

#pragma unroll
    for (int j = 0; j < 8; j++)
        sA[j][n] = A[(k0 + j) * 256 + n];
    __syncthreads();

    float acc[8];
#pragma unroll
    for (int j = 0; j < 8; j++) acc[j] = 0.f;

    for (int t = 0; t < 256; t++) {
        float wv = __ldg(&Wc[t * 256 + n]);
#pragma unroll
        for (int j = 0; j < 8; j++)
            acc[j] = fmaf(sA[j][t], wv, acc[j]);
    }
#pragma unroll
    for (int j = 0; j < 8; j++) {
        __nv_bfloat16 h = __float2bfloat16(acc[j]);
        __nv_bfloat16 l = __float2bfloat16(acc[j] - __bfloat162float(h));
        wth[(size_t)m * 65536 + n * 256 + k0 + j] = h;
        wtl[(size_t)m * 65536 + n * 256 + k0 + j] = l;
    }
}

__global__ __launch_bounds__(256)
void fuse_b(const float* __restrict__ f0b, const float* __restrict__ f1b,
            const float* __restrict__ cw, const float* __restrict__ cb,
            float* __restrict__ beff)
{
    __shared__ float sB[256];
    const int m = blockIdx.x;
    const int layer = m >> 1, which = m & 1;
    const float* b  = (which == 0 ? f0b : f1b) + (size_t)layer * 256;
    const float* Wc = cw + (size_t)layer * 65536;
    const int n = threadIdx.x;
    sB[n] = b[n];
    __syncthreads();
    float acc = __ldg(&cb[layer * 256 + n]);
#pragma unroll 8
    for (int t = 0; t < 256; t++)
        acc = fmaf(sB[t], __ldg(&Wc[t * 256 + n]), acc);
    beff[m * 256 + n] = acc;
}

// ---------------- mma.sync bf16 split GEMM with ldmatrix ----------------
#define KC      32
#define LDS_A   40                  // halves; 80B row stride, 16B aligned
#define TILE_HB (128 * LDS_A * 2)   // 10240
#define STAGE_B (4 * TILE_HB)       // 40960

__device__ __forceinline__ void mma16816(float* c, const uint32_t* a, const uint32_t* b)
{
    asm volatile(
        "mma.sync.aligned.m16n8k16.row.col.f32.bf16.bf16.f32 "
        "{%0,%1,%2,%3}, {%4,%5,%6,%7}, {%8,%9}, {%0,%1,%2,%3};"
        : "+f"(c[0]), "+f"(c[1]), "+f"(c[2]), "+f"(c[3])
        : "r"(a[0]), "r"(a[1]), "r"(a[2]), "r"(a[3]), "r"(b[0]), "r"(b[1]));
}
__device__ __forceinline__ void ldm_x4(uint32_t* r, uint32_t addr)
{
    asm volatile("ldmatrix.sync.aligned.m8n8.x4.shared.b16 {%0,%1,%2,%3}, [%4];"
                 : "=r"(r[0]), "=r"(r[1]), "=r"(r[2]), "=r"(r[3]) : "r"(addr));
}
__device__ __forceinline__ void cpa16(uint32_t dst, const void* src, int sz)
{
    asm volatile("cp.async.ca.shared.global [%0], [%1], 16, %2;"
                 :: "r"(dst), "l"(src), "r"(sz));
}
__device__ __forceinline__ void cpa_commit() { asm volatile("cp.async.commit_group;"); }
template <int N>
__device__ __forceinline__ void cpa_wait() {
    asm volatile("cp.async.wait_group %0;" :: "n"(N));
}

__global__ __launch_bounds__(256, 2)
void tc_gemm(const __nv_bfloat16* __restrict__ Ah, const __nv_bfloat16* __restrict__ Al,
             const __nv_bfloat16* __restrict__ Wth, const __nv_bfloat16* __restrict__ Wtl,
             const float* __restrict__ bias, float* __restrict__ C,
             int M, const int* __restrict__ rowmap)
{
    extern __shared__ __align__(16) char smem_dyn[];

    const int tid  = threadIdx.x;
    const int wid  = tid >> 5;
    const int lane = tid & 31;
    const int bm   = blockIdx.x * 128;
    const int bn   = blockIdx.y * 128;
    const int wr   = wid & 1;
    const int wc   = wid >> 1;
    const int qp = lane >> 2;
    const int qr = lane & 3;

    const uint32_t smem_u = (uint32_t)__cvta_generic_to_shared(smem_dyn);

    // ldmatrix lane->row/col mapping (in halves)
    const int a_lr = (lane & 7) + ((lane >> 3) & 1) * 8;   // row within m16
    const int a_kc = ((lane >> 4) & 1) * 8;                // k offset 0/8
    const int b_lr = (lane & 7) + ((lane >> 4) & 1) * 8;   // row within n16 pair
    const int b_kc = ((lane >> 3) & 1) * 8;                // k offset 0/8

    float acc[4][4][4];
#pragma unroll
    for (int i = 0; i < 4; i++)
#pragma unroll
        for (int j = 0; j < 4; j++)
#pragma unroll
            for (int r = 0; r < 4; r++) acc[i][j][r] = 0.f;

    int arow[2];
#pragma unroll
    for (int i = 0; i < 2; i++) {
        int u = i * 256 + tid;
        int r = u >> 2;
        int grow = bm + r;
        arow[i] = rowmap ? __ldg(&rowmap[grow]) : (grow < M ? grow : -1);
    }

    auto load_stage = [&](int st, int k0) {
        const uint32_t sb = smem_u + st * STAGE_B;
#pragma unroll
        for (int i = 0; i < 2; i++) {
            int u = i * 256 + tid;
            int r = u >> 2;
            int cq = (u & 3);
            uint32_t doff = (uint32_t)(r * (LDS_A * 2) + cq * 16);
            int khalf = k0 + cq * 8;
            int sz = (arow[i] >= 0) ? 16 : 0;
            const __nv_bfloat16* gh = Ah + ((size_t)(arow[i] >= 0 ? arow[i] : 0)) * HID + khalf;
            const __nv_bfloat16* gl = Al + ((size_t)(arow[i] >= 0 ? arow[i] : 0)) * HID + khalf;
            cpa16(sb + 0 * TILE_HB + doff, gh, sz);
            cpa16(sb + 1 * TILE_HB + doff, gl, sz);
            cpa16(sb + 2 * TILE_HB + doff, Wth + (size_t)(bn + r) * HID + khalf, 16);
            cpa16(sb + 3 * TILE_HB + doff, Wtl + (size_t)(bn + r) * HID + khalf, 16);
        }
    };

    auto compute_stage = [&](int st) {
        const uint32_t sAh = smem_u + st * STAGE_B + 0 * TILE_HB;
        const uint32_t sAl = smem_u + st * STAGE_B + 1 * TILE_HB;
        const uint32_t sBh = smem_u + st * STAGE_B + 2 * TILE_HB;
        const uint32_t sBl = smem_u + st * STAGE_B + 3 * TILE_HB;
#pragma unroll
        for (int ks = 0; ks < KC; ks += 16) {
            // A fragments via ldmatrix.x4 (hi and lo), 4 m-tiles
            uint32_t fAh[4][4], fAl[4][4];
#pragma unroll
            for (int mt = 0; mt < 4; mt++) {
                uint32_t off = (uint32_t)(((wr * 64 + mt * 16 + a_lr) * LDS_A
                                           + ks + a_kc) * 2);
                ldm_x4(fAh[mt], sAh + off);
                ldm_x4(fAl[mt], sAl + off);
            }
            // B hi fragments: 2 ldmatrix.x4 cover 4 n8 tiles
            uint32_t fBh[4][2];
#pragma unroll
            for (int j = 0; j < 2; j++) {
                uint32_t off = (uint32_t)(((wc * 32 + j * 16 + b_lr) * LDS_A
                                           + ks + b_kc) * 2);
                uint32_t r[4];
                ldm_x4(r, sBh + off);
                fBh[j * 2 + 0][0] = r[0]; fBh[j * 2 + 0][1] = r[1];
                fBh[j * 2 + 1][0] = r[2]; fBh[j * 2 + 1][1] = r[3];
            }
#pragma unroll
            for (int mt = 0; mt < 4; mt++)
#pragma unroll
                for (int nt = 0; nt < 4; nt++) {
                    mma16816(acc[mt][nt], fAh[mt], fBh[nt]);
                    mma16816(acc[mt][nt], fAl[mt], fBh[nt]);
                }
            // B lo fragments
            uint32_t fBl[4][2];
#pragma unroll
            for (int j = 0; j < 2; j++) {
                uint32_t off = (uint32_t)(((wc * 32 + j * 16 + b_lr) * LDS_A
                                           + ks + b_kc) * 2);
                uint32_t r[4];
                ldm_x4(r, sBl + off);
                fBl[j * 2 + 0][0] = r[0]; fBl[j * 2 + 0][1] = r[1];
                fBl[j * 2 + 1][0] = r[2]; fBl[j * 2 + 1][1] = r[3];
            }
#pragma unroll
            for (int mt = 0; mt < 4; mt++)
#pragma unroll
                for (int nt = 0; nt < 4; nt++)
                    mma16816(acc[mt][nt], fAh[mt], fBl[nt]);
        }
    };

    load_stage(0, 0);
    cpa_commit();
#pragma unroll
    for (int c = 0; c < 8; c++) {
        if (c < 7) {
            load_stage((c + 1) & 1, (c + 1) * KC);
            cpa_commit();
            cpa_wait<1>();
        } else {
            cpa_wait<0>();
        }
        __syncthreads();
        compute_stage(c & 1);
        __syncthreads();
    }

#pragma unroll
    for (int mt = 0; mt < 4; mt++) {
        int grow0 = bm + wr * 64 + mt * 16 + qp;
        int grow1 = grow0 + 8;
        int row0 = rowmap ? __ldg(&rowmap[grow0]) : grow0;
        int row1 = rowmap ? __ldg(&rowmap[grow1]) : grow1;
        bool v0 = rowmap ? true : (grow0 < M);
        bool v1 = rowmap ? true : (grow1 < M);
#pragma unroll
        for (int nt = 0; nt < 4; nt++) {
            int col = bn + wc * 32 + nt * 8 + qr * 2;
            float b0 = __ldg(&bias[col]);
            float b1 = __ldg(&bias[col + 1]);
            if (v0) *(float2*)(C + (size_t)row0 * HID + col) =
                        make_float2(acc[mt][nt][0] + b0, acc[mt][nt][1] + b1);
            if (v1) *(float2*)(C + (size_t)row1 * HID + col) =
                        make_float2(acc[mt][nt][2] + b0, acc[mt][nt][3] + b1);
        }
    }
}

// ---------------- fp32 -> bf16 hi/lo pair (initial x only) ----------------
__global__ void to_pair(const float* __restrict__ in,
                        __nv_bfloat16* __restrict__ hi, __nv_bfloat16* __restrict__ lo,
                        int n4)
{
    int t = blockIdx.x * blockDim.x + threadIdx.x;
    if (t >= n4) return;
    float4 v = ((const float4*)in)[t];
    __nv_bfloat16 h0 = __float2bfloat16(v.x);
    __nv_bfloat16 h1 = __float2bfloat16(v.y);
    __nv_bfloat16 h2 = __float2bfloat16(v.z);
    __nv_bfloat16 h3 = __float2bfloat16(v.w);
    __nv_bfloat162 hp0(h0, h1), hp1(h2, h3);
    __nv_bfloat162 lp0(__float2bfloat16(v.x - __bfloat162float(h0)),
                       __float2bfloat16(v.y - __bfloat162float(h1)));
    __nv_bfloat162 lp1(__float2bfloat16(v.z - __bfloat162float(h2)),
                       __float2bfloat16(v.w - __bfloat162float(h3)));
    ((__nv_bfloat162*)hi)[t * 2 + 0] = hp0;
    ((__nv_bfloat162*)hi)[t * 2 + 1] = hp1;
    ((__nv_bfloat162*)lo)[t * 2 + 0] = lp0;
    ((__nv_bfloat162*)lo)[t * 2 + 1] = lp1;
}

// ---------------- CSR build ----------------
__global__ void csr_zero(int* __restrict__ cnt)
{
    int t = blockIdx.x * blockDim.x + threadIdx.x;
    if (t < NNODES) cnt[t] = 0;
}
__global__ void csr_hist(const int* __restrict__ dst, int* __restrict__ cnt)
{
    int t = blockIdx.x * blockDim.x + threadIdx.x;
    if (t < NEDGES) atomicAdd(&cnt[__ldg(&dst[t])], 1);
}
__global__ __launch_bounds__(256)
void scan_blk(const int* __restrict__ cnt, int* __restrict__ off, int* __restrict__ bsum)
{
    __shared__ int sh[256];
    int idx = blockIdx.x * 256 + threadIdx.x;
    int v = (idx < NNODES) ? cnt[idx] : 0;
    sh[threadIdx.x] = v;
    __syncthreads();
#pragma unroll
    for (int d = 1; d < 256; d <<= 1) {
        int t = (threadIdx.x >= d) ? sh[threadIdx.x - d] : 0;
        __syncthreads();
        sh[threadIdx.x] += t;
        __syncthreads();
    }
    if (idx < NNODES) off[idx] = sh[threadIdx.x] - v;
    if (threadIdx.x == 255) bsum[blockIdx.x] = sh[255];
}
__global__ __launch_bounds__(256)
void scan_top(const int* __restrict__ bsum, int* __restrict__ boff)
{
    __shared__ int sh[256];
    int v = (threadIdx.x < SCAN_BLKS) ? bsum[threadIdx.x] : 0;
    sh[threadIdx.x] = v;
    __syncthreads();
#pragma unroll
    for (int d = 1; d < 256; d <<= 1) {
        int t = (threadIdx.x >= d) ? sh[threadIdx.x - d] : 0;
        __syncthreads();
        sh[threadIdx.x] += t;
        __syncthreads();
    }
    if (threadIdx.x < SCAN_BLKS) boff[threadIdx.x] = sh[threadIdx.x] - v;
}
__global__ void scan_add(int* __restrict__ off, const int* __restrict__ boff,
                         int* __restrict__ cnt)
{
    int idx = blockIdx.x * 256 + threadIdx.x;
    if (idx < NNODES) {
        off[idx] += boff[blockIdx.x];
        cnt[idx] = 0;
    }
    if (idx == 0) off[NNODES] = NEDGES;
}
__global__ void csr_fill(const int* __restrict__ src, const int* __restrict__ dst,
                         const int* __restrict__ off, int* __restrict__ cur,
                         int* __restrict__ eid)
{
    int t = blockIdx.x * blockDim.x + threadIdx.x;
    if (t >= NEDGES) return;
    int d = __ldg(&dst[t]);
    int p = atomicAdd(&cur[d], 1);
    eid[__ldg(&off[d]) + p] = __ldg(&src[t]);
}

// ---------------- pull segment-sum (+ optional fused outputs) ----------------
__global__ __launch_bounds__(256)
void pull_sum(const float* __restrict__ h, const int* __restrict__ off,
              const int* __restrict__ eid, float* __restrict__ xc,
              __nv_bfloat16* __restrict__ xh, __nv_bfloat16* __restrict__ xl,
              int wf32, int wpair)
{
    int node = blockIdx.x * 8 + (threadIdx.x >> 5);
    if (node >= NNODES) return;
    int lane = threadIdx.x & 31;
    int s0 = __ldg(&off[node]);
    int s1 = __ldg(&off[node + 1]);
    float4 a0 = make_float4(0.f, 0.f, 0.f, 0.f), a1 = a0;
    const float4* H = (const float4*)h;
    int i = s0;
    for (; i + 1 < s1; i += 2) {
        int e0 = __ldg(&eid[i]);
        int e1 = __ldg(&eid[i + 1]);
        const float4* r0 = H + (size_t)e0 * 64 + lane * 2;
        const float4* r1 = H + (size_t)e1 * 64 + lane * 2;
        float4 v00 = __ldg(r0), v01 = __ldg(r0 + 1);
        float4 v10 = __ldg(r1), v11 = __ldg(r1 + 1);
        a0.x += v00.x; a0.y += v00.y; a0.z += v00.z; a0.w += v00.w;
        a1.x += v01.x; a1.y += v01.y; a1.z += v01.z; a1.w += v01.w;
        a0.x += v10.x; a0.y += v10.y; a0.z += v10.z; a0.w += v10.w;
        a1.x += v11.x; a1.y += v11.y; a1.z += v11.z; a1.w += v11.w;
    }
    if (i < s1) {
        int e0 = __ldg(&eid[i]);
        const float4* r0 = H + (size_t)e0 * 64 + lane * 2;
        float4 v00 = __ldg(r0), v01 = __ldg(r0 + 1);
        a0.x += v00.x; a0.y += v00.y; a0.z += v00.z; a0.w += v00.w;
        a1.x += v01.x; a1.y += v01.y; a1.z += v01.z; a1.w += v01.w;
    }
    if (wf32) {
        float4* X = (float4*)xc + (size_t)node * 64 + lane * 2;
        X[0] = a0; X[1] = a1;
    }
    if (wpair) {
        float vals[8] = {a0.x, a0.y, a0.z, a0.w, a1.x, a1.y, a1.z, a1.w};
        __nv_bfloat16 hv[8], lv[8];
#pragma unroll
        for (int j = 0; j < 8; j++) {
            hv[j] = __float2bfloat16(vals[j]);
            lv[j] = __float2bfloat16(vals[j] - __bfloat162float(hv[j]));
        }
        *(uint4*)(xh + (size_t)node * HID + lane * 8) = *(uint4*)hv;
        *(uint4*)(xl + (size_t)node * HID + lane * 8) = *(uint4*)lv;
    }
}

__global__ void gather_out(const float* __restrict__ x, const int* __restrict__ pos,
                           float4* __restrict__ out)
{
    int t = blockIdx.x * blockDim.x + threadIdx.x;
    if (t >= NROWS_LBL * 64) return;
    int r = t >> 6, c = t & 63;
    int row = __ldg(&pos[r]);
    out[t] = *(const float4*)(x + (size_t)row * HID + (c << 2));
}

// ---------------- launch ----------------
extern "C" void kernel_launch(void* const* d_in, const int* in_sizes, int n_in,
                              void* d_out, int out_size)
{
    (void)in_sizes; (void)n_in; (void)out_size;
    const float* x    = (const float*)d_in[0];
    const float* f0w  = (const float*)d_in[1];
    const float* f0b  = (const float*)d_in[2];
    const float* f1w  = (const float*)d_in[3];
    const float* f1b  = (const float*)d_in[4];
    const float* cw   = (const float*)d_in[5];
    const float* cb   = (const float*)d_in[6];
    const int*   esrc = (const int*)d_in[7];
    const int*   edst = (const int*)d_in[8];
    const int*   pos  = (const int*)d_in[9];

    float *h, *xc, *beff;
    __nv_bfloat16 *xh, *xl, *wth, *wtl;
    int *cnt, *off, *eid, *bsum, *boff;
    cudaGetSymbolAddress((void**)&h,    g_h);
    cudaGetSymbolAddress((void**)&xc,   g_x);
    cudaGetSymbolAddress((void**)&xh,   g_xh);
    cudaGetSymbolAddress((void**)&xl,   g_xl);
    cudaGetSymbolAddress((void**)&wth,  g_wth);
    cudaGetSymbolAddress((void**)&wtl,  g_wtl);
    cudaGetSymbolAddress((void**)&beff, g_beff);
    cudaGetSymbolAddress((void**)&cnt,  g_cnt);
    cudaGetSymbolAddress((void**)&off,  g_off);
    cudaGetSymbolAddress((void**)&eid,  g_eid);
    cudaGetSymbolAddress((void**)&bsum, g_bsum);
    cudaGetSymbolAddress((void**)&boff, g_boff);

    const int SMEM_DYN = 2 * STAGE_B;   // 81920
    cudaFuncSetAttribute(tc_gemm, cudaFuncAttributeMaxDynamicSharedMemorySize, SMEM_DYN);

    const int n4 = NNODES * HID / 4;
    dim3 gN((NNODES + 127) / 128, 2);
    dim3 gL(NROWS_LBL / 128, 2);

    fuse_w<<<dim3(32, 6), 256>>>(f0w, f1w, cw, wth, wtl);
    fuse_b<<<6, 256>>>(f0b, f1b, cw, cb, beff);
    csr_zero<<<(NNODES + 255) / 256, 256>>>(cnt);
    csr_hist<<<(NEDGES + 255) / 256, 256>>>(edst, cnt);
    scan_blk<<<SCAN_BLKS, 256>>>(cnt, off, bsum);
    scan_top<<<1, 256>>>(bsum, boff);
    scan_add<<<SCAN_BLKS, 256>>>(off, boff, cnt);
    csr_fill<<<(NEDGES + 255) / 256, 256>>>(esrc, edst, off, cnt, eid);

    to_pair<<<(n4 + 255) / 256, 256>>>(x, xh, xl, n4);

    for (int i = 0; i < 3; i++) {
        const size_t wo0 = (size_t)(i * 2 + 0) * 65536;
        const size_t wo1 = (size_t)(i * 2 + 1) * 65536;
        tc_gemm<<<gN, 256, SMEM_DYN>>>(xh, xl, wth + wo0, wtl + wo0,
                                       beff + (i * 2 + 0) * 256, h, NNODES, nullptr);
        tc_gemm<<<gL, 256, SMEM_DYN>>>(xh, xl, wth + wo1, wtl + wo1,
                                       beff + (i * 2 + 1) * 256, h, NROWS_LBL, pos);
        int last = (i == 2);
        pull_sum<<<(NNODES + 7) / 8, 256>>>(h, off, eid, xc, xh, xl,
                                            last ? 1 : 0, last ? 0 : 1);
    }
    gather_out<<<(NROWS_LBL * 64 + 255) / 256, 256>>>(xc, pos, (float4*)d_out);
}

// round 9
// speedup vs baseline: 1.3101x; 1.1614x over previous
#include <cuda_runtime.h>
#include <cuda_bf16.h>
#include <cstdint>
#include <cstddef>

#define HID        256
#define NNODES     50000
#define NEDGES     800000
#define NROWS_LBL  8192
#define SCAN_BLKS  196
#define GN_BLKS    391              // ceil(50000/128)
#define GL_BLKS    64               // 8192/128

// ---------------- scratch ----------------
__device__ float g_h [(size_t)NNODES * HID];
__device__ __nv_bfloat16 g_xh[(size_t)NNODES * HID];
__device__ __nv_bfloat16 g_xl[(size_t)NNODES * HID];
__device__ __nv_bfloat16 g_wth[6 * 65536];
__device__ __nv_bfloat16 g_wtl[6 * 65536];
__device__ float g_beff[6 * 256];
__device__ int g_cnt[NNODES];
__device__ int g_flag[NNODES];
__device__ int g_off[NNODES + 1];
__device__ int g_eid[NEDGES];
__device__ int g_bsum[SCAN_BLKS];
__device__ int g_boff[SCAN_BLKS];

// ---------------- fused weight precompute ----------------
__global__ __launch_bounds__(256)
void fuse_w(const float* __restrict__ f0w, const float* __restrict__ f1w,
            const float* __restrict__ cw,
            __nv_bfloat16* __restrict__ wth, __nv_bfloat16* __restrict__ wtl)
{
    __shared__ float sA[8][256];
    const int m = blockIdx.y;
    const int layer = m >> 1, which = m & 1;
    const float* A  = (which == 0 ? f0w : f1w) + (size_t)layer * 65536;
    const float* Wc = cw + (size_t)layer * 65536;
    const int k0 = blockIdx.x * 8;
    const int n  = threadIdx.x;

#pragma unroll
    for (int j = 0; j < 8; j++)
        sA[j][n] = A[(k0 + j) * 256 + n];
    __syncthreads();

    float acc[8];
#pragma unroll
    for (int j = 0; j < 8; j++) acc[j] = 0.f;

    for (int t = 0; t < 256; t++) {
        float wv = __ldg(&Wc[t * 256 + n]);
#pragma unroll
        for (int j = 0; j < 8; j++)
            acc[j] = fmaf(sA[j][t], wv, acc[j]);
    }
#pragma unroll
    for (int j = 0; j < 8; j++) {
        __nv_bfloat16 h = __float2bfloat16(acc[j]);
        __nv_bfloat16 l = __float2bfloat16(acc[j] - __bfloat162float(h));
        wth[(size_t)m * 65536 + n * 256 + k0 + j] = h;
        wtl[(size_t)m * 65536 + n * 256 + k0 + j] = l;
    }
}

__global__ __launch_bounds__(256)
void fuse_b(const float* __restrict__ f0b, const float* __restrict__ f1b,
            const float* __restrict__ cw, const float* __restrict__ cb,
            float* __restrict__ beff)
{
    __shared__ float sB[256];
    const int m = blockIdx.x;
    const int layer = m >> 1, which = m & 1;
    const float* b  = (which == 0 ? f0b : f1b) + (size_t)layer * 256;
    const float* Wc = cw + (size_t)layer * 65536;
    const int n = threadIdx.x;
    sB[n] = b[n];
    __syncthreads();
    float acc = __ldg(&cb[layer * 256 + n]);
#pragma unroll 8
    for (int t = 0; t < 256; t++)
        acc = fmaf(sB[t], __ldg(&Wc[t * 256 + n]), acc);
    beff[m * 256 + n] = acc;
}

// ---------------- mma.sync bf16 split GEMM with ldmatrix (merged launch) ----------------
#define KC      32
#define LDS_A   40
#define TILE_HB (128 * LDS_A * 2)   // 10240
#define STAGE_B (4 * TILE_HB)       // 40960

__device__ __forceinline__ void mma16816(float* c, const uint32_t* a, const uint32_t* b)
{
    asm volatile(
        "mma.sync.aligned.m16n8k16.row.col.f32.bf16.bf16.f32 "
        "{%0,%1,%2,%3}, {%4,%5,%6,%7}, {%8,%9}, {%0,%1,%2,%3};"
        : "+f"(c[0]), "+f"(c[1]), "+f"(c[2]), "+f"(c[3])
        : "r"(a[0]), "r"(a[1]), "r"(a[2]), "r"(a[3]), "r"(b[0]), "r"(b[1]));
}
__device__ __forceinline__ void ldm_x4(uint32_t* r, uint32_t addr)
{
    asm volatile("ldmatrix.sync.aligned.m8n8.x4.shared.b16 {%0,%1,%2,%3}, [%4];"
                 : "=r"(r[0]), "=r"(r[1]), "=r"(r[2]), "=r"(r[3]) : "r"(addr));
}
__device__ __forceinline__ void cpa16(uint32_t dst, const void* src, int sz)
{
    asm volatile("cp.async.ca.shared.global [%0], [%1], 16, %2;"
                 :: "r"(dst), "l"(src), "r"(sz));
}
__device__ __forceinline__ void cpa_commit() { asm volatile("cp.async.commit_group;"); }
template <int N>
__device__ __forceinline__ void cpa_wait() {
    asm volatile("cp.async.wait_group %0;" :: "n"(N));
}

// grid.x = GN_BLKS + GL_BLKS.
//   blockIdx.x <  GN_BLKS : normal tile, weights W0eff, stores skipped on flagged rows
//   blockIdx.x >= GN_BLKS : labeled tile, rows = pos[...], weights W1eff
__global__ __launch_bounds__(256, 2)
void tc_gemm(const __nv_bfloat16* __restrict__ Ah, const __nv_bfloat16* __restrict__ Al,
             const __nv_bfloat16* __restrict__ Wth0, const __nv_bfloat16* __restrict__ Wtl0,
             const __nv_bfloat16* __restrict__ Wth1, const __nv_bfloat16* __restrict__ Wtl1,
             const float* __restrict__ bias0, const float* __restrict__ bias1,
             float* __restrict__ C,
             const int* __restrict__ pos, const int* __restrict__ flag)
{
    extern __shared__ __align__(16) char smem_dyn[];

    const bool lbl = (blockIdx.x >= GN_BLKS);
    const __nv_bfloat16* Wth = lbl ? Wth1 : Wth0;
    const __nv_bfloat16* Wtl = lbl ? Wtl1 : Wtl0;
    const float* bias        = lbl ? bias1 : bias0;
    const int* rowmap        = lbl ? pos : nullptr;
    const int bm = (lbl ? (blockIdx.x - GN_BLKS) : blockIdx.x) * 128;

    const int tid  = threadIdx.x;
    const int wid  = tid >> 5;
    const int lane = tid & 31;
    const int bn   = blockIdx.y * 128;
    const int wr   = wid & 1;
    const int wc   = wid >> 1;
    const int qp = lane >> 2;
    const int qr = lane & 3;

    const uint32_t smem_u = (uint32_t)__cvta_generic_to_shared(smem_dyn);

    const int a_lr = (lane & 7) + ((lane >> 3) & 1) * 8;
    const int a_kc = ((lane >> 4) & 1) * 8;
    const int b_lr = (lane & 7) + ((lane >> 4) & 1) * 8;
    const int b_kc = ((lane >> 3) & 1) * 8;

    float acc[4][4][4];
#pragma unroll
    for (int i = 0; i < 4; i++)
#pragma unroll
        for (int j = 0; j < 4; j++)
#pragma unroll
            for (int r = 0; r < 4; r++) acc[i][j][r] = 0.f;

    int arow[2];
#pragma unroll
    for (int i = 0; i < 2; i++) {
        int u = i * 256 + tid;
        int r = u >> 2;
        int grow = bm + r;
        arow[i] = rowmap ? __ldg(&rowmap[grow]) : (grow < NNODES ? grow : -1);
    }

    auto load_stage = [&](int st, int k0) {
        const uint32_t sb = smem_u + st * STAGE_B;
#pragma unroll
        for (int i = 0; i < 2; i++) {
            int u = i * 256 + tid;
            int r = u >> 2;
            int cq = (u & 3);
            uint32_t doff = (uint32_t)(r * (LDS_A * 2) + cq * 16);
            int khalf = k0 + cq * 8;
            int sz = (arow[i] >= 0) ? 16 : 0;
            const __nv_bfloat16* gh = Ah + ((size_t)(arow[i] >= 0 ? arow[i] : 0)) * HID + khalf;
            const __nv_bfloat16* gl = Al + ((size_t)(arow[i] >= 0 ? arow[i] : 0)) * HID + khalf;
            cpa16(sb + 0 * TILE_HB + doff, gh, sz);
            cpa16(sb + 1 * TILE_HB + doff, gl, sz);
            cpa16(sb + 2 * TILE_HB + doff, Wth + (size_t)(bn + r) * HID + khalf, 16);
            cpa16(sb + 3 * TILE_HB + doff, Wtl + (size_t)(bn + r) * HID + khalf, 16);
        }
    };

    auto compute_stage = [&](int st) {
        const uint32_t sAh = smem_u + st * STAGE_B + 0 * TILE_HB;
        const uint32_t sAl = smem_u + st * STAGE_B + 1 * TILE_HB;
        const uint32_t sBh = smem_u + st * STAGE_B + 2 * TILE_HB;
        const uint32_t sBl = smem_u + st * STAGE_B + 3 * TILE_HB;
#pragma unroll
        for (int ks = 0; ks < KC; ks += 16) {
            uint32_t fAh[4][4], fAl[4][4];
#pragma unroll
            for (int mt = 0; mt < 4; mt++) {
                uint32_t off = (uint32_t)(((wr * 64 + mt * 16 + a_lr) * LDS_A
                                           + ks + a_kc) * 2);
                ldm_x4(fAh[mt], sAh + off);
                ldm_x4(fAl[mt], sAl + off);
            }
            uint32_t fBh[4][2];
#pragma unroll
            for (int j = 0; j < 2; j++) {
                uint32_t off = (uint32_t)(((wc * 32 + j * 16 + b_lr) * LDS_A
                                           + ks + b_kc) * 2);
                uint32_t r[4];
                ldm_x4(r, sBh + off);
                fBh[j * 2 + 0][0] = r[0]; fBh[j * 2 + 0][1] = r[1];
                fBh[j * 2 + 1][0] = r[2]; fBh[j * 2 + 1][1] = r[3];
            }
#pragma unroll
            for (int mt = 0; mt < 4; mt++)
#pragma unroll
                for (int nt = 0; nt < 4; nt++) {
                    mma16816(acc[mt][nt], fAh[mt], fBh[nt]);
                    mma16816(acc[mt][nt], fAl[mt], fBh[nt]);
                }
            uint32_t fBl[4][2];
#pragma unroll
            for (int j = 0; j < 2; j++) {
                uint32_t off = (uint32_t)(((wc * 32 + j * 16 + b_lr) * LDS_A
                                           + ks + b_kc) * 2);
                uint32_t r[4];
                ldm_x4(r, sBl + off);
                fBl[j * 2 + 0][0] = r[0]; fBl[j * 2 + 0][1] = r[1];
                fBl[j * 2 + 1][0] = r[2]; fBl[j * 2 + 1][1] = r[3];
            }
#pragma unroll
            for (int mt = 0; mt < 4; mt++)
#pragma unroll
                for (int nt = 0; nt < 4; nt++)
                    mma16816(acc[mt][nt], fAh[mt], fBl[nt]);
        }
    };

    load_stage(0, 0);
    cpa_commit();
#pragma unroll
    for (int c = 0; c < 8; c++) {
        if (c < 7) {
            load_stage((c + 1) & 1, (c + 1) * KC);
            cpa_commit();
            cpa_wait<1>();
        } else {
            cpa_wait<0>();
        }
        __syncthreads();
        compute_stage(c & 1);
        __syncthreads();
    }

#pragma unroll
    for (int mt = 0; mt < 4; mt++) {
        int grow0 = bm + wr * 64 + mt * 16 + qp;
        int grow1 = grow0 + 8;
        int row0, row1;
        bool v0, v1;
        if (lbl) {
            row0 = __ldg(&rowmap[grow0]);
            row1 = __ldg(&rowmap[grow1]);
            v0 = true; v1 = true;
        } else {
            row0 = grow0; row1 = grow1;
            v0 = (grow0 < NNODES) && (__ldg(&flag[grow0]) == 0);
            v1 = (grow1 < NNODES) && (__ldg(&flag[grow1]) == 0);
        }
#pragma unroll
        for (int nt = 0; nt < 4; nt++) {
            int col = bn + wc * 32 + nt * 8 + qr * 2;
            float b0 = __ldg(&bias[col]);
            float b1 = __ldg(&bias[col + 1]);
            if (v0) *(float2*)(C + (size_t)row0 * HID + col) =
                        make_float2(acc[mt][nt][0] + b0, acc[mt][nt][1] + b1);
            if (v1) *(float2*)(C + (size_t)row1 * HID + col) =
                        make_float2(acc[mt][nt][2] + b0, acc[mt][nt][3] + b1);
        }
    }
}

// ---------------- fp32 -> bf16 hi/lo pair (initial x only) ----------------
__global__ void to_pair(const float* __restrict__ in,
                        __nv_bfloat16* __restrict__ hi, __nv_bfloat16* __restrict__ lo,
                        int n4)
{
    int t = blockIdx.x * blockDim.x + threadIdx.x;
    if (t >= n4) return;
    float4 v = ((const float4*)in)[t];
    __nv_bfloat16 h0 = __float2bfloat16(v.x);
    __nv_bfloat16 h1 = __float2bfloat16(v.y);
    __nv_bfloat16 h2 = __float2bfloat16(v.z);
    __nv_bfloat16 h3 = __float2bfloat16(v.w);
    __nv_bfloat162 hp0(h0, h1), hp1(h2, h3);
    __nv_bfloat162 lp0(__float2bfloat16(v.x - __bfloat162float(h0)),
                       __float2bfloat16(v.y - __bfloat162float(h1)));
    __nv_bfloat162 lp1(__float2bfloat16(v.z - __bfloat162float(h2)),
                       __float2bfloat16(v.w - __bfloat162float(h3)));
    ((__nv_bfloat162*)hi)[t * 2 + 0] = hp0;
    ((__nv_bfloat162*)hi)[t * 2 + 1] = hp1;
    ((__nv_bfloat162*)lo)[t * 2 + 0] = lp0;
    ((__nv_bfloat162*)lo)[t * 2 + 1] = lp1;
}

// ---------------- CSR build + flags ----------------
__global__ void set_flag(const int* __restrict__ pos, int* __restrict__ flag)
{
    int t = blockIdx.x * blockDim.x + threadIdx.x;
    if (t < NROWS_LBL) flag[__ldg(&pos[t])] = 1;
}
__global__ void csr_hist(const int* __restrict__ dst, int* __restrict__ cnt)
{
    int t = blockIdx.x * blockDim.x + threadIdx.x;
    if (t < NEDGES) atomicAdd(&cnt[__ldg(&dst[t])], 1);
}
__global__ __launch_bounds__(256)
void scan_blk(const int* __restrict__ cnt, int* __restrict__ off, int* __restrict__ bsum)
{
    __shared__ int sh[256];
    int idx = blockIdx.x * 256 + threadIdx.x;
    int v = (idx < NNODES) ? cnt[idx] : 0;
    sh[threadIdx.x] = v;
    __syncthreads();
#pragma unroll
    for (int d = 1; d < 256; d <<= 1) {
        int t = (threadIdx.x >= d) ? sh[threadIdx.x - d] : 0;
        __syncthreads();
        sh[threadIdx.x] += t;
        __syncthreads();
    }
    if (idx < NNODES) off[idx] = sh[threadIdx.x] - v;
    if (threadIdx.x == 255) bsum[blockIdx.x] = sh[255];
}
__global__ __launch_bounds__(256)
void scan_top(const int* __restrict__ bsum, int* __restrict__ boff)
{
    __shared__ int sh[256];
    int v = (threadIdx.x < SCAN_BLKS) ? bsum[threadIdx.x] : 0;
    sh[threadIdx.x] = v;
    __syncthreads();
#pragma unroll
    for (int d = 1; d < 256; d <<= 1) {
        int t = (threadIdx.x >= d) ? sh[threadIdx.x - d] : 0;
        __syncthreads();
        sh[threadIdx.x] += t;
        __syncthreads();
    }
    if (threadIdx.x < SCAN_BLKS) boff[threadIdx.x] = sh[threadIdx.x] - v;
}
__global__ void scan_add(int* __restrict__ off, const int* __restrict__ boff,
                         int* __restrict__ cnt)
{
    int idx = blockIdx.x * 256 + threadIdx.x;
    if (idx < NNODES) {
        off[idx] += boff[blockIdx.x];
        cnt[idx] = 0;
    }
    if (idx == 0) off[NNODES] = NEDGES;
}
__global__ void csr_fill(const int* __restrict__ src, const int* __restrict__ dst,
                         const int* __restrict__ off, int* __restrict__ cur,
                         int* __restrict__ eid)
{
    int t = blockIdx.x * blockDim.x + threadIdx.x;
    if (t >= NEDGES) return;
    int d = __ldg(&dst[t]);
    int p = atomicAdd(&cur[d], 1);
    eid[__ldg(&off[d]) + p] = __ldg(&src[t]);
}

// ---------------- pull segment-sum: bf16-pair out (layers 0,1) ----------------
__global__ __launch_bounds__(256)
void pull_pair(const float* __restrict__ h, const int* __restrict__ off,
               const int* __restrict__ eid,
               __nv_bfloat16* __restrict__ xh, __nv_bfloat16* __restrict__ xl)
{
    int node = blockIdx.x * 8 + (threadIdx.x >> 5);
    if (node >= NNODES) return;
    int lane = threadIdx.x & 31;
    int s0 = __ldg(&off[node]);
    int s1 = __ldg(&off[node + 1]);
    float4 a0 = make_float4(0.f, 0.f, 0.f, 0.f), a1 = a0;
    const float4* H = (const float4*)h;
    int i = s0;
    for (; i + 1 < s1; i += 2) {
        int e0 = __ldg(&eid[i]);
        int e1 = __ldg(&eid[i + 1]);
        const float4* r0 = H + (size_t)e0 * 64 + lane * 2;
        const float4* r1 = H + (size_t)e1 * 64 + lane * 2;
        float4 v00 = __ldg(r0), v01 = __ldg(r0 + 1);
        float4 v10 = __ldg(r1), v11 = __ldg(r1 + 1);
        a0.x += v00.x; a0.y += v00.y; a0.z += v00.z; a0.w += v00.w;
        a1.x += v01.x; a1.y += v01.y; a1.z += v01.z; a1.w += v01.w;
        a0.x += v10.x; a0.y += v10.y; a0.z += v10.z; a0.w += v10.w;
        a1.x += v11.x; a1.y += v11.y; a1.z += v11.z; a1.w += v11.w;
    }
    if (i < s1) {
        int e0 = __ldg(&eid[i]);
        const float4* r0 = H + (size_t)e0 * 64 + lane * 2;
        float4 v00 = __ldg(r0), v01 = __ldg(r0 + 1);
        a0.x += v00.x; a0.y += v00.y; a0.z += v00.z; a0.w += v00.w;
        a1.x += v01.x; a1.y += v01.y; a1.z += v01.z; a1.w += v01.w;
    }
    float vals[8] = {a0.x, a0.y, a0.z, a0.w, a1.x, a1.y, a1.z, a1.w};
    __nv_bfloat16 hv[8], lv[8];
#pragma unroll
    for (int j = 0; j < 8; j++) {
        hv[j] = __float2bfloat16(vals[j]);
        lv[j] = __float2bfloat16(vals[j] - __bfloat162float(hv[j]));
    }
    *(uint4*)(xh + (size_t)node * HID + lane * 8) = *(uint4*)hv;
    *(uint4*)(xl + (size_t)node * HID + lane * 8) = *(uint4*)lv;
}

// ---------------- last-layer pull: only pos rows, straight to d_out ----------------
__global__ __launch_bounds__(256)
void pull_out(const float* __restrict__ h, const int* __restrict__ off,
              const int* __restrict__ eid, const int* __restrict__ pos,
              float* __restrict__ out)
{
    int slot = blockIdx.x * 8 + (threadIdx.x >> 5);
    if (slot >= NROWS_LBL) return;
    int lane = threadIdx.x & 31;
    int node = __ldg(&pos[slot]);
    int s0 = __ldg(&off[node]);
    int s1 = __ldg(&off[node + 1]);
    float4 a0 = make_float4(0.f, 0.f, 0.f, 0.f), a1 = a0;
    const float4* H = (const float4*)h;
    int i = s0;
    for (; i + 1 < s1; i += 2) {
        int e0 = __ldg(&eid[i]);
        int e1 = __ldg(&eid[i + 1]);
        const float4* r0 = H + (size_t)e0 * 64 + lane * 2;
        const float4* r1 = H + (size_t)e1 * 64 + lane * 2;
        float4 v00 = __ldg(r0), v01 = __ldg(r0 + 1);
        float4 v10 = __ldg(r1), v11 = __ldg(r1 + 1);
        a0.x += v00.x; a0.y += v00.y; a0.z += v00.z; a0.w += v00.w;
        a1.x += v01.x; a1.y += v01.y; a1.z += v01.z; a1.w += v01.w;
        a0.x += v10.x; a0.y += v10.y; a0.z += v10.z; a0.w += v10.w;
        a1.x += v11.x; a1.y += v11.y; a1.z += v11.z; a1.w += v11.w;
    }
    if (i < s1) {
        int e0 = __ldg(&eid[i]);
        const float4* r0 = H + (size_t)e0 * 64 + lane * 2;
        float4 v00 = __ldg(r0), v01 = __ldg(r0 + 1);
        a0.x += v00.x; a0.y += v00.y; a0.z += v00.z; a0.w += v00.w;
        a1.x += v01.x; a1.y += v01.y; a1.z += v01.z; a1.w += v01.w;
    }
    float4* O = (float4*)out + (size_t)slot * 64 + lane * 2;
    O[0] = a0; O[1] = a1;
}

// ---------------- launch ----------------
extern "C" void kernel_launch(void* const* d_in, const int* in_sizes, int n_in,
                              void* d_out, int out_size)
{
    (void)in_sizes; (void)n_in; (void)out_size;
    const float* x    = (const float*)d_in[0];
    const float* f0w  = (const float*)d_in[1];
    const float* f0b  = (const float*)d_in[2];
    const float* f1w  = (const float*)d_in[3];
    const float* f1b  = (const float*)d_in[4];
    const float* cw   = (const float*)d_in[5];
    const float* cb   = (const float*)d_in[6];
    const int*   esrc = (const int*)d_in[7];
    const int*   edst = (const int*)d_in[8];
    const int*   pos  = (const int*)d_in[9];

    float *h, *beff;
    __nv_bfloat16 *xh, *xl, *wth, *wtl;
    int *cnt, *flag, *off, *eid, *bsum, *boff;
    cudaGetSymbolAddress((void**)&h,    g_h);
    cudaGetSymbolAddress((void**)&xh,   g_xh);
    cudaGetSymbolAddress((void**)&xl,   g_xl);
    cudaGetSymbolAddress((void**)&wth,  g_wth);
    cudaGetSymbolAddress((void**)&wtl,  g_wtl);
    cudaGetSymbolAddress((void**)&beff, g_beff);
    cudaGetSymbolAddress((void**)&cnt,  g_cnt);
    cudaGetSymbolAddress((void**)&flag, g_flag);
    cudaGetSymbolAddress((void**)&off,  g_off);
    cudaGetSymbolAddress((void**)&eid,  g_eid);
    cudaGetSymbolAddress((void**)&bsum, g_bsum);
    cudaGetSymbolAddress((void**)&boff, g_boff);

    const int SMEM_DYN = 2 * STAGE_B;   // 81920
    cudaFuncSetAttribute(tc_gemm, cudaFuncAttributeMaxDynamicSharedMemorySize, SMEM_DYN);

    const int n4 = NNODES * HID / 4;
    dim3 gMerged(GN_BLKS + GL_BLKS, 2);

    fuse_w<<<dim3(32, 6), 256>>>(f0w, f1w, cw, wth, wtl);
    fuse_b<<<6, 256>>>(f0b, f1b, cw, cb, beff);
    cudaMemsetAsync(cnt,  0, NNODES * sizeof(int));
    cudaMemsetAsync(flag, 0, NNODES * sizeof(int));
    set_flag<<<(NROWS_LBL + 255) / 256, 256>>>(pos, flag);
    csr_hist<<<(NEDGES + 255) / 256, 256>>>(edst, cnt);
    scan_blk<<<SCAN_BLKS, 256>>>(cnt, off, bsum);
    scan_top<<<1, 256>>>(bsum, boff);
    scan_add<<<SCAN_BLKS, 256>>>(off, boff, cnt);
    csr_fill<<<(NEDGES + 255) / 256, 256>>>(esrc, edst, off, cnt, eid);

    to_pair<<<(n4 + 255) / 256, 256>>>(x, xh, xl, n4);

    for (int i = 0; i < 3; i++) {
        const size_t wo0 = (size_t)(i * 2 + 0) * 65536;
        const size_t wo1 = (size_t)(i * 2 + 1) * 65536;
        tc_gemm<<<gMerged, 256, SMEM_DYN>>>(xh, xl,
                                            wth + wo0, wtl + wo0,
                                            wth + wo1, wtl + wo1,
                                            beff + (i * 2 + 0) * 256,
                                            beff + (i * 2 + 1) * 256,
                                            h, pos, flag);
        if (i < 2)
            pull_pair<<<(NNODES + 7) / 8, 256>>>(h, off, eid, xh, xl);
        else
            pull_out<<<(NROWS_LBL + 7) / 8, 256>>>(h, off, eid, pos, (float*)d_out);
    }
}

// round 10
// speedup vs baseline: 1.4819x; 1.1311x over previous
#include <cuda_runtime.h>
#include <cuda_fp16.h>
#include <cstdint>
#include <cstddef>

#define HID        256
#define NNODES     50000
#define NEDGES     800000
#define NROWS_LBL  8192
#define SCAN_BLKS  196
#define GN_BLKS    391              // ceil(50000/128)
#define GL_BLKS    64               // 8192/128

// ---------------- scratch ----------------
__device__ float g_h [(size_t)NNODES * HID];
__device__ __half g_xh[(size_t)NNODES * HID];
__device__ __half g_xl[(size_t)NNODES * HID];
__device__ __half g_wt[6 * 65536];           // fused W^T [n][k], fp16
__device__ float g_beff[6 * 256];
__device__ int g_cnt[NNODES];
__device__ int g_flag[NNODES];
__device__ int g_off[NNODES + 1];
__device__ int g_eid[NEDGES];
__device__ int g_bsum[SCAN_BLKS];
__device__ int g_boff[SCAN_BLKS];

// ---------------- fused weight precompute ----------------
__global__ __launch_bounds__(256)
void fuse_w(const float* __restrict__ f0w, const float* __restrict__ f1w,
            const float* __restrict__ cw, __half* __restrict__ wt)
{
    __shared__ float sA[8][256];
    const int m = blockIdx.y;
    const int layer = m >> 1, which = m & 1;
    const float* A  = (which == 0 ? f0w : f1w) + (size_t)layer * 65536;
    const float* Wc = cw + (size_t)layer * 65536;
    const int k0 = blockIdx.x * 8;
    const int n  = threadIdx.x;

#pragma unroll
    for (int j = 0; j < 8; j++)
        sA[j][n] = A[(k0 + j) * 256 + n];
    __syncthreads();

    float acc[8];
#pragma unroll
    for (int j = 0; j < 8; j++) acc[j] = 0.f;

    for (int t = 0; t < 256; t++) {
        float wv = __ldg(&Wc[t * 256 + n]);
#pragma unroll
        for (int j = 0; j < 8; j++)
            acc[j] = fmaf(sA[j][t], wv, acc[j]);
    }
#pragma unroll
    for (int j = 0; j < 8; j++)
        wt[(size_t)m * 65536 + n * 256 + k0 + j] = __float2half_rn(acc[j]);
}

__global__ __launch_bounds__(256)
void fuse_b(const float* __restrict__ f0b, const float* __restrict__ f1b,
            const float* __restrict__ cw, const float* __restrict__ cb,
            float* __restrict__ beff)
{
    __shared__ float sB[256];
    const int m = blockIdx.x;
    const int layer = m >> 1, which = m & 1;
    const float* b  = (which == 0 ? f0b : f1b) + (size_t)layer * 256;
    const float* Wc = cw + (size_t)layer * 65536;
    const int n = threadIdx.x;
    sB[n] = b[n];
    __syncthreads();
    float acc = __ldg(&cb[layer * 256 + n]);
#pragma unroll 8
    for (int t = 0; t < 256; t++)
        acc = fmaf(sB[t], __ldg(&Wc[t * 256 + n]), acc);
    beff[m * 256 + n] = acc;
}

// ---------------- mma.sync fp16 split GEMM, 3-stage pipeline ----------------
#define KC      32
#define LDS_A   40                  // halves; 80B row stride
#define TILE_HB (128 * LDS_A * 2)   // 10240 B
#define STAGE_B (3 * TILE_HB)       // Ah Al Bh = 30720 B
#define NSTAGE  3

__device__ __forceinline__ void mma16816(float* c, const uint32_t* a, const uint32_t* b)
{
    asm volatile(
        "mma.sync.aligned.m16n8k16.row.col.f32.f16.f16.f32 "
        "{%0,%1,%2,%3}, {%4,%5,%6,%7}, {%8,%9}, {%0,%1,%2,%3};"
        : "+f"(c[0]), "+f"(c[1]), "+f"(c[2]), "+f"(c[3])
        : "r"(a[0]), "r"(a[1]), "r"(a[2]), "r"(a[3]), "r"(b[0]), "r"(b[1]));
}
__device__ __forceinline__ void ldm_x4(uint32_t* r, uint32_t addr)
{
    asm volatile("ldmatrix.sync.aligned.m8n8.x4.shared.b16 {%0,%1,%2,%3}, [%4];"
                 : "=r"(r[0]), "=r"(r[1]), "=r"(r[2]), "=r"(r[3]) : "r"(addr));
}
__device__ __forceinline__ void cpa16(uint32_t dst, const void* src, int sz)
{
    asm volatile("cp.async.ca.shared.global [%0], [%1], 16, %2;"
                 :: "r"(dst), "l"(src), "r"(sz));
}
__device__ __forceinline__ void cpa_commit() { asm volatile("cp.async.commit_group;"); }
template <int N>
__device__ __forceinline__ void cpa_wait() {
    asm volatile("cp.async.wait_group %0;" :: "n"(N));
}

// grid.x = GN_BLKS + GL_BLKS (normal tiles, then labeled tiles).
__global__ __launch_bounds__(256, 2)
void tc_gemm(const __half* __restrict__ Ah, const __half* __restrict__ Al,
             const __half* __restrict__ Wt0, const __half* __restrict__ Wt1,
             const float* __restrict__ bias0, const float* __restrict__ bias1,
             float* __restrict__ C,
             const int* __restrict__ pos, const int* __restrict__ flag)
{
    extern __shared__ __align__(16) char smem_dyn[];

    const bool lbl = (blockIdx.x >= GN_BLKS);
    const __half* Wt  = lbl ? Wt1 : Wt0;
    const float* bias = lbl ? bias1 : bias0;
    const int* rowmap = lbl ? pos : nullptr;
    const int bm = (lbl ? (blockIdx.x - GN_BLKS) : blockIdx.x) * 128;

    const int tid  = threadIdx.x;
    const int wid  = tid >> 5;
    const int lane = tid & 31;
    const int bn   = blockIdx.y * 128;
    const int wr   = wid & 1;
    const int wc   = wid >> 1;
    const int qp = lane >> 2;
    const int qr = lane & 3;

    const uint32_t smem_u = (uint32_t)__cvta_generic_to_shared(smem_dyn);

    const int a_lr = (lane & 7) + ((lane >> 3) & 1) * 8;
    const int a_kc = ((lane >> 4) & 1) * 8;
    const int b_lr = (lane & 7) + ((lane >> 4) & 1) * 8;
    const int b_kc = ((lane >> 3) & 1) * 8;

    float acc[4][4][4];
#pragma unroll
    for (int i = 0; i < 4; i++)
#pragma unroll
        for (int j = 0; j < 4; j++)
#pragma unroll
            for (int r = 0; r < 4; r++) acc[i][j][r] = 0.f;

    int arow[2];
#pragma unroll
    for (int i = 0; i < 2; i++) {
        int u = i * 256 + tid;
        int r = u >> 2;
        int grow = bm + r;
        arow[i] = rowmap ? __ldg(&rowmap[grow]) : (grow < NNODES ? grow : -1);
    }

    auto load_stage = [&](int st, int k0) {
        const uint32_t sb = smem_u + st * STAGE_B;
#pragma unroll
        for (int i = 0; i < 2; i++) {
            int u = i * 256 + tid;
            int r = u >> 2;
            int cq = (u & 3);
            uint32_t doff = (uint32_t)(r * (LDS_A * 2) + cq * 16);
            int khalf = k0 + cq * 8;
            int sz = (arow[i] >= 0) ? 16 : 0;
            const __half* gh = Ah + ((size_t)(arow[i] >= 0 ? arow[i] : 0)) * HID + khalf;
            const __half* gl = Al + ((size_t)(arow[i] >= 0 ? arow[i] : 0)) * HID + khalf;
            cpa16(sb + 0 * TILE_HB + doff, gh, sz);
            cpa16(sb + 1 * TILE_HB + doff, gl, sz);
            cpa16(sb + 2 * TILE_HB + doff, Wt + (size_t)(bn + r) * HID + khalf, 16);
        }
    };

    auto compute_stage = [&](int st) {
        const uint32_t sAh = smem_u + st * STAGE_B + 0 * TILE_HB;
        const uint32_t sAl = smem_u + st * STAGE_B + 1 * TILE_HB;
        const uint32_t sBh = smem_u + st * STAGE_B + 2 * TILE_HB;
#pragma unroll
        for (int ks = 0; ks < KC; ks += 16) {
            uint32_t fAh[4][4], fAl[4][4];
#pragma unroll
            for (int mt = 0; mt < 4; mt++) {
                uint32_t off = (uint32_t)(((wr * 64 + mt * 16 + a_lr) * LDS_A
                                           + ks + a_kc) * 2);
                ldm_x4(fAh[mt], sAh + off);
                ldm_x4(fAl[mt], sAl + off);
            }
            uint32_t fB[4][2];
#pragma unroll
            for (int j = 0; j < 2; j++) {
                uint32_t off = (uint32_t)(((wc * 32 + j * 16 + b_lr) * LDS_A
                                           + ks + b_kc) * 2);
                uint32_t r[4];
                ldm_x4(r, sBh + off);
                fB[j * 2 + 0][0] = r[0]; fB[j * 2 + 0][1] = r[1];
                fB[j * 2 + 1][0] = r[2]; fB[j * 2 + 1][1] = r[3];
            }
#pragma unroll
            for (int mt = 0; mt < 4; mt++)
#pragma unroll
                for (int nt = 0; nt < 4; nt++) {
                    mma16816(acc[mt][nt], fAh[mt], fB[nt]);
                    mma16816(acc[mt][nt], fAl[mt], fB[nt]);
                }
        }
    };

    // 3-stage pipeline, single sync per chunk
    load_stage(0, 0);
    cpa_commit();
    load_stage(1, KC);
    cpa_commit();
#pragma unroll
    for (int c = 0; c < 8; c++) {
        if (c < 7) cpa_wait<1>(); else cpa_wait<0>();
        __syncthreads();
        if (c < 6) {
            load_stage((c + 2) % NSTAGE, (c + 2) * KC);
            cpa_commit();
        }
        compute_stage(c % NSTAGE);
    }

#pragma unroll
    for (int mt = 0; mt < 4; mt++) {
        int grow0 = bm + wr * 64 + mt * 16 + qp;
        int grow1 = grow0 + 8;
        int row0, row1;
        bool v0, v1;
        if (lbl) {
            row0 = __ldg(&rowmap[grow0]);
            row1 = __ldg(&rowmap[grow1]);
            v0 = true; v1 = true;
        } else {
            row0 = grow0; row1 = grow1;
            v0 = (grow0 < NNODES) && (__ldg(&flag[grow0]) == 0);
            v1 = (grow1 < NNODES) && (__ldg(&flag[grow1]) == 0);
        }
#pragma unroll
        for (int nt = 0; nt < 4; nt++) {
            int col = bn + wc * 32 + nt * 8 + qr * 2;
            float b0 = __ldg(&bias[col]);
            float b1 = __ldg(&bias[col + 1]);
            if (v0) *(float2*)(C + (size_t)row0 * HID + col) =
                        make_float2(acc[mt][nt][0] + b0, acc[mt][nt][1] + b1);
            if (v1) *(float2*)(C + (size_t)row1 * HID + col) =
                        make_float2(acc[mt][nt][2] + b0, acc[mt][nt][3] + b1);
        }
    }
}

// ---------------- fp32 -> fp16 hi/lo pair (initial x only) ----------------
__global__ void to_pair(const float* __restrict__ in,
                        __half* __restrict__ hi, __half* __restrict__ lo, int n4)
{
    int t = blockIdx.x * blockDim.x + threadIdx.x;
    if (t >= n4) return;
    float4 v = ((const float4*)in)[t];
    float vv[4] = {v.x, v.y, v.z, v.w};
    __half hv[4], lv[4];
#pragma unroll
    for (int j = 0; j < 4; j++) {
        hv[j] = __float2half_rn(vv[j]);
        lv[j] = __float2half_rn(vv[j] - __half2float(hv[j]));
    }
    ((uint2*)hi)[t] = *(uint2*)hv;
    ((uint2*)lo)[t] = *(uint2*)lv;
}

// ---------------- CSR build + flags ----------------
__global__ void set_flag(const int* __restrict__ pos, int* __restrict__ flag)
{
    int t = blockIdx.x * blockDim.x + threadIdx.x;
    if (t < NROWS_LBL) flag[__ldg(&pos[t])] = 1;
}
__global__ void csr_hist(const int* __restrict__ dst, int* __restrict__ cnt)
{
    int t = blockIdx.x * blockDim.x + threadIdx.x;
    if (t < NEDGES) atomicAdd(&cnt[__ldg(&dst[t])], 1);
}
__global__ __launch_bounds__(256)
void scan_blk(const int* __restrict__ cnt, int* __restrict__ off, int* __restrict__ bsum)
{
    __shared__ int sh[256];
    int idx = blockIdx.x * 256 + threadIdx.x;
    int v = (idx < NNODES) ? cnt[idx] : 0;
    sh[threadIdx.x] = v;
    __syncthreads();
#pragma unroll
    for (int d = 1; d < 256; d <<= 1) {
        int t = (threadIdx.x >= d) ? sh[threadIdx.x - d] : 0;
        __syncthreads();
        sh[threadIdx.x] += t;
        __syncthreads();
    }
    if (idx < NNODES) off[idx] = sh[threadIdx.x] - v;
    if (threadIdx.x == 255) bsum[blockIdx.x] = sh[255];
}
__global__ __launch_bounds__(256)
void scan_top(const int* __restrict__ bsum, int* __restrict__ boff)
{
    __shared__ int sh[256];
    int v = (threadIdx.x < SCAN_BLKS) ? bsum[threadIdx.x] : 0;
    sh[threadIdx.x] = v;
    __syncthreads();
#pragma unroll
    for (int d = 1; d < 256; d <<= 1) {
        int t = (threadIdx.x >= d) ? sh[threadIdx.x - d] : 0;
        __syncthreads();
        sh[threadIdx.x] += t;
        __syncthreads();
    }
    if (threadIdx.x < SCAN_BLKS) boff[threadIdx.x] = sh[threadIdx.x] - v;
}
__global__ void scan_add(int* __restrict__ off, const int* __restrict__ boff,
                         int* __restrict__ cnt)
{
    int idx = blockIdx.x * 256 + threadIdx.x;
    if (idx < NNODES) {
        off[idx] += boff[blockIdx.x];
        cnt[idx] = 0;
    }
    if (idx == 0) off[NNODES] = NEDGES;
}
__global__ void csr_fill(const int* __restrict__ src, const int* __restrict__ dst,
                         const int* __restrict__ off, int* __restrict__ cur,
                         int* __restrict__ eid)
{
    int t = blockIdx.x * blockDim.x + threadIdx.x;
    if (t >= NEDGES) return;
    int d = __ldg(&dst[t]);
    int p = atomicAdd(&cur[d], 1);
    eid[__ldg(&off[d]) + p] = __ldg(&src[t]);
}

// ---------------- pull segment-sum: fp16-pair out (layers 0,1) ----------------
__global__ __launch_bounds__(256)
void pull_pair(const float* __restrict__ h, const int* __restrict__ off,
               const int* __restrict__ eid,
               __half* __restrict__ xh, __half* __restrict__ xl)
{
    int node = blockIdx.x * 8 + (threadIdx.x >> 5);
    if (node >= NNODES) return;
    int lane = threadIdx.x & 31;
    int s0 = __ldg(&off[node]);
    int s1 = __ldg(&off[node + 1]);
    float4 a0 = make_float4(0.f, 0.f, 0.f, 0.f), a1 = a0;
    const float4* H = (const float4*)h;
    int i = s0;
    for (; i + 1 < s1; i += 2) {
        int e0 = __ldg(&eid[i]);
        int e1 = __ldg(&eid[i + 1]);
        const float4* r0 = H + (size_t)e0 * 64 + lane * 2;
        const float4* r1 = H + (size_t)e1 * 64 + lane * 2;
        float4 v00 = __ldg(r0), v01 = __ldg(r0 + 1);
        float4 v10 = __ldg(r1), v11 = __ldg(r1 + 1);
        a0.x += v00.x; a0.y += v00.y; a0.z += v00.z; a0.w += v00.w;
        a1.x += v01.x; a1.y += v01.y; a1.z += v01.z; a1.w += v01.w;
        a0.x += v10.x; a0.y += v10.y; a0.z += v10.z; a0.w += v10.w;
        a1.x += v11.x; a1.y += v11.y; a1.z += v11.z; a1.w += v11.w;
    }
    if (i < s1) {
        int e0 = __ldg(&eid[i]);
        const float4* r0 = H + (size_t)e0 * 64 + lane * 2;
        float4 v00 = __ldg(r0), v01 = __ldg(r0 + 1);
        a0.x += v00.x; a0.y += v00.y; a0.z += v00.z; a0.w += v00.w;
        a1.x += v01.x; a1.y += v01.y; a1.z += v01.z; a1.w += v01.w;
    }
    float vals[8] = {a0.x, a0.y, a0.z, a0.w, a1.x, a1.y, a1.z, a1.w};
    __half hv[8], lv[8];
#pragma unroll
    for (int j = 0; j < 8; j++) {
        hv[j] = __float2half_rn(vals[j]);
        lv[j] = __float2half_rn(vals[j] - __half2float(hv[j]));
    }
    *(uint4*)(xh + (size_t)node * HID + lane * 8) = *(uint4*)hv;
    *(uint4*)(xl + (size_t)node * HID + lane * 8) = *(uint4*)lv;
}

// ---------------- last-layer pull: only pos rows, straight to d_out ----------------
__global__ __launch_bounds__(256)
void pull_out(const float* __restrict__ h, const int* __restrict__ off,
              const int* __restrict__ eid, const int* __restrict__ pos,
              float* __restrict__ out)
{
    int slot = blockIdx.x * 8 + (threadIdx.x >> 5);
    if (slot >= NROWS_LBL) return;
    int lane = threadIdx.x & 31;
    int node = __ldg(&pos[slot]);
    int s0 = __ldg(&off[node]);
    int s1 = __ldg(&off[node + 1]);
    float4 a0 = make_float4(0.f, 0.f, 0.f, 0.f), a1 = a0;
    const float4* H = (const float4*)h;
    int i = s0;
    for (; i + 1 < s1; i += 2) {
        int e0 = __ldg(&eid[i]);
        int e1 = __ldg(&eid[i + 1]);
        const float4* r0 = H + (size_t)e0 * 64 + lane * 2;
        const float4* r1 = H + (size_t)e1 * 64 + lane * 2;
        float4 v00 = __ldg(r0), v01 = __ldg(r0 + 1);
        float4 v10 = __ldg(r1), v11 = __ldg(r1 + 1);
        a0.x += v00.x; a0.y += v00.y; a0.z += v00.z; a0.w += v00.w;
        a1.x += v01.x; a1.y += v01.y; a1.z += v01.z; a1.w += v01.w;
        a0.x += v10.x; a0.y += v10.y; a0.z += v10.z; a0.w += v10.w;
        a1.x += v11.x; a1.y += v11.y; a1.z += v11.z; a1.w += v11.w;
    }
    if (i < s1) {
        int e0 = __ldg(&eid[i]);
        const float4* r0 = H + (size_t)e0 * 64 + lane * 2;
        float4 v00 = __ldg(r0), v01 = __ldg(r0 + 1);
        a0.x += v00.x; a0.y += v00.y; a0.z += v00.z; a0.w += v00.w;
        a1.x += v01.x; a1.y += v01.y; a1.z += v01.z; a1.w += v01.w;
    }
    float4* O = (float4*)out + (size_t)slot * 64 + lane * 2;
    O[0] = a0; O[1] = a1;
}

// ---------------- launch ----------------
extern "C" void kernel_launch(void* const* d_in, const int* in_sizes, int n_in,
                              void* d_out, int out_size)
{
    (void)in_sizes; (void)n_in; (void)out_size;
    const float* x    = (const float*)d_in[0];
    const float* f0w  = (const float*)d_in[1];
    const float* f0b  = (const float*)d_in[2];
    const float* f1w  = (const float*)d_in[3];
    const float* f1b  = (const float*)d_in[4];
    const float* cw   = (const float*)d_in[5];
    const float* cb   = (const float*)d_in[6];
    const int*   esrc = (const int*)d_in[7];
    const int*   edst = (const int*)d_in[8];
    const int*   pos  = (const int*)d_in[9];

    float *h, *beff;
    __half *xh, *xl, *wt;
    int *cnt, *flag, *off, *eid, *bsum, *boff;
    cudaGetSymbolAddress((void**)&h,    g_h);
    cudaGetSymbolAddress((void**)&xh,   g_xh);
    cudaGetSymbolAddress((void**)&xl,   g_xl);
    cudaGetSymbolAddress((void**)&wt,   g_wt);
    cudaGetSymbolAddress((void**)&beff, g_beff);
    cudaGetSymbolAddress((void**)&cnt,  g_cnt);
    cudaGetSymbolAddress((void**)&flag, g_flag);
    cudaGetSymbolAddress((void**)&off,  g_off);
    cudaGetSymbolAddress((void**)&eid,  g_eid);
    cudaGetSymbolAddress((void**)&bsum, g_bsum);
    cudaGetSymbolAddress((void**)&boff, g_boff);

    const int SMEM_DYN = NSTAGE * STAGE_B;   // 92160
    cudaFuncSetAttribute(tc_gemm, cudaFuncAttributeMaxDynamicSharedMemorySize, SMEM_DYN);

    const int n4 = NNODES * HID / 4;
    dim3 gMerged(GN_BLKS + GL_BLKS, 2);

    fuse_w<<<dim3(32, 6), 256>>>(f0w, f1w, cw, wt);
    fuse_b<<<6, 256>>>(f0b, f1b, cw, cb, beff);
    cudaMemsetAsync(cnt,  0, NNODES * sizeof(int));
    cudaMemsetAsync(flag, 0, NNODES * sizeof(int));
    set_flag<<<(NROWS_LBL + 255) / 256, 256>>>(pos, flag);
    csr_hist<<<(NEDGES + 255) / 256, 256>>>(edst, cnt);
    scan_blk<<<SCAN_BLKS, 256>>>(cnt, off, bsum);
    scan_top<<<1, 256>>>(bsum, boff);
    scan_add<<<SCAN_BLKS, 256>>>(off, boff, cnt);
    csr_fill<<<(NEDGES + 255) / 256, 256>>>(esrc, edst, off, cnt, eid);

    to_pair<<<(n4 + 255) / 256, 256>>>(x, xh, xl, n4);

    for (int i = 0; i < 3; i++) {
        const size_t wo0 = (size_t)(i * 2 + 0) * 65536;
        const size_t wo1 = (size_t)(i * 2 + 1) * 65536;
        tc_gemm<<<gMerged, 256, SMEM_DYN>>>(xh, xl,
                                            wt + wo0, wt + wo1,
                                            beff + (i * 2 + 0) * 256,
                                            beff + (i * 2 + 1) * 256,
                                            h, pos, flag);
        if (i < 2)
            pull_pair<<<(NNODES + 7) / 8, 256>>>(h, off, eid, xh, xl);
        else
            pull_out<<<(NROWS_LBL + 7) / 8, 256>>>(h, off, eid, pos, (float*)d_out);
    }
}

// round 12
// speedup vs baseline: 1.7459x; 1.1782x over previous
#include <cuda_runtime.h>
#include <cuda_fp16.h>
#include <cstdint>
#include <cstddef>

#define HID        256
#define NNODES     50000
#define NEDGES     800000
#define NROWS_LBL  8192
#define SCAN_BLKS  196
#define GN_BLKS    391              // ceil(50000/128)
#define GL_BLKS    64               // 8192/128

// ---------------- scratch ----------------
__device__ __half g_h [(size_t)NNODES * HID];   // conv output, fp16 (gather-bound)
__device__ __half g_xh[(size_t)NNODES * HID];
__device__ __half g_xl[(size_t)NNODES * HID];
__device__ __half g_wt[6 * 65536];              // fused W^T [n][k], fp16
__device__ float g_beff[6 * 256];
__device__ int g_cnt[NNODES];
__device__ int g_flag[NNODES];
__device__ int g_off[NNODES + 1];
__device__ int g_eid[NEDGES];
__device__ int g_bsum[SCAN_BLKS];
__device__ int g_boff[SCAN_BLKS];

// ---------------- fused weight precompute ----------------
__global__ __launch_bounds__(256)
void fuse_w(const float* __restrict__ f0w, const float* __restrict__ f1w,
            const float* __restrict__ cw, __half* __restrict__ wt)
{
    __shared__ float sA[8][256];
    const int m = blockIdx.y;
    const int layer = m >> 1, which = m & 1;
    const float* A  = (which == 0 ? f0w : f1w) + (size_t)layer * 65536;
    const float* Wc = cw + (size_t)layer * 65536;
    const int k0 = blockIdx.x * 8;
    const int n  = threadIdx.x;

#pragma unroll
    for (int j = 0; j < 8; j++)
        sA[j][n] = A[(k0 + j) * 256 + n];
    __syncthreads();

    float acc[8];
#pragma unroll
    for (int j = 0; j < 8; j++) acc[j] = 0.f;

    for (int t = 0; t < 256; t++) {
        float wv = __ldg(&Wc[t * 256 + n]);
#pragma unroll
        for (int j = 0; j < 8; j++)
            acc[j] = fmaf(sA[j][t], wv, acc[j]);
    }
#pragma unroll
    for (int j = 0; j < 8; j++)
        wt[(size_t)m * 65536 + n * 256 + k0 + j] = __float2half_rn(acc[j]);
}

__global__ __launch_bounds__(256)
void fuse_b(const float* __restrict__ f0b, const float* __restrict__ f1b,
            const float* __restrict__ cw, const float* __restrict__ cb,
            float* __restrict__ beff)
{
    __shared__ float sB[256];
    const int m = blockIdx.x;
    const int layer = m >> 1, which = m & 1;
    const float* b  = (which == 0 ? f0b : f1b) + (size_t)layer * 256;
    const float* Wc = cw + (size_t)layer * 65536;
    const int n = threadIdx.x;
    sB[n] = b[n];
    __syncthreads();
    float acc = __ldg(&cb[layer * 256 + n]);
#pragma unroll 8
    for (int t = 0; t < 256; t++)
        acc = fmaf(sB[t], __ldg(&Wc[t * 256 + n]), acc);
    beff[m * 256 + n] = acc;
}

// ---------------- mma.sync fp16 split GEMM, 3-stage pipeline ----------------
#define KC      32
#define LDS_A   40
#define TILE_HB (128 * LDS_A * 2)   // 10240 B
#define STAGE_B (3 * TILE_HB)       // 30720 B
#define NSTAGE  3

__device__ __forceinline__ void mma16816(float* c, const uint32_t* a, const uint32_t* b)
{
    asm volatile(
        "mma.sync.aligned.m16n8k16.row.col.f32.f16.f16.f32 "
        "{%0,%1,%2,%3}, {%4,%5,%6,%7}, {%8,%9}, {%0,%1,%2,%3};"
        : "+f"(c[0]), "+f"(c[1]), "+f"(c[2]), "+f"(c[3])
        : "r"(a[0]), "r"(a[1]), "r"(a[2]), "r"(a[3]), "r"(b[0]), "r"(b[1]));
}
__device__ __forceinline__ void ldm_x4(uint32_t* r, uint32_t addr)
{
    asm volatile("ldmatrix.sync.aligned.m8n8.x4.shared.b16 {%0,%1,%2,%3}, [%4];"
                 : "=r"(r[0]), "=r"(r[1]), "=r"(r[2]), "=r"(r[3]) : "r"(addr));
}
__device__ __forceinline__ void cpa16(uint32_t dst, const void* src, int sz)
{
    asm volatile("cp.async.ca.shared.global [%0], [%1], 16, %2;"
                 :: "r"(dst), "l"(src), "r"(sz));
}
__device__ __forceinline__ void cpa_commit() { asm volatile("cp.async.commit_group;"); }
template <int N>
__device__ __forceinline__ void cpa_wait() {
    asm volatile("cp.async.wait_group %0;" :: "n"(N));
}

// grid.x = GN_BLKS + GL_BLKS (normal tiles, then labeled tiles).
__global__ __launch_bounds__(256, 2)
void tc_gemm(const __half* __restrict__ Ah, const __half* __restrict__ Al,
             const __half* __restrict__ Wt0, const __half* __restrict__ Wt1,
             const float* __restrict__ bias0, const float* __restrict__ bias1,
             __half* __restrict__ C,
             const int* __restrict__ pos, const int* __restrict__ flag)
{
    extern __shared__ __align__(16) char smem_dyn[];

    const bool lbl = (blockIdx.x >= GN_BLKS);
    const __half* Wt  = lbl ? Wt1 : Wt0;
    const float* bias = lbl ? bias1 : bias0;
    const int* rowmap = lbl ? pos : nullptr;
    const int bm = (lbl ? (blockIdx.x - GN_BLKS) : blockIdx.x) * 128;

    const int tid  = threadIdx.x;
    const int wid  = tid >> 5;
    const int lane = tid & 31;
    const int bn   = blockIdx.y * 128;
    const int wr   = wid & 1;
    const int wc   = wid >> 1;
    const int qp = lane >> 2;
    const int qr = lane & 3;

    const uint32_t smem_u = (uint32_t)__cvta_generic_to_shared(smem_dyn);

    const int a_lr = (lane & 7) + ((lane >> 3) & 1) * 8;
    const int a_kc = ((lane >> 4) & 1) * 8;
    const int b_lr = (lane & 7) + ((lane >> 4) & 1) * 8;
    const int b_kc = ((lane >> 3) & 1) * 8;

    float acc[4][4][4];
#pragma unroll
    for (int i = 0; i < 4; i++)
#pragma unroll
        for (int j = 0; j < 4; j++)
#pragma unroll
            for (int r = 0; r < 4; r++) acc[i][j][r] = 0.f;

    int arow[2];
#pragma unroll
    for (int i = 0; i < 2; i++) {
        int u = i * 256 + tid;
        int r = u >> 2;
        int grow = bm + r;
        arow[i] = rowmap ? __ldg(&rowmap[grow]) : (grow < NNODES ? grow : -1);
    }

    auto load_stage = [&](int st, int k0) {
        const uint32_t sb = smem_u + st * STAGE_B;
#pragma unroll
        for (int i = 0; i < 2; i++) {
            int u = i * 256 + tid;
            int r = u >> 2;
            int cq = (u & 3);
            uint32_t doff = (uint32_t)(r * (LDS_A * 2) + cq * 16);
            int khalf = k0 + cq * 8;
            int sz = (arow[i] >= 0) ? 16 : 0;
            const __half* gh = Ah + ((size_t)(arow[i] >= 0 ? arow[i] : 0)) * HID + khalf;
            const __half* gl = Al + ((size_t)(arow[i] >= 0 ? arow[i] : 0)) * HID + khalf;
            cpa16(sb + 0 * TILE_HB + doff, gh, sz);
            cpa16(sb + 1 * TILE_HB + doff, gl, sz);
            cpa16(sb + 2 * TILE_HB + doff, Wt + (size_t)(bn + r) * HID + khalf, 16);
        }
    };

    auto compute_stage = [&](int st) {
        const uint32_t sAh = smem_u + st * STAGE_B + 0 * TILE_HB;
        const uint32_t sAl = smem_u + st * STAGE_B + 1 * TILE_HB;
        const uint32_t sBh = smem_u + st * STAGE_B + 2 * TILE_HB;
#pragma unroll
        for (int ks = 0; ks < KC; ks += 16) {
            uint32_t fAh[4][4], fAl[4][4];
#pragma unroll
            for (int mt = 0; mt < 4; mt++) {
                uint32_t off = (uint32_t)(((wr * 64 + mt * 16 + a_lr) * LDS_A
                                           + ks + a_kc) * 2);
                ldm_x4(fAh[mt], sAh + off);
                ldm_x4(fAl[mt], sAl + off);
            }
            uint32_t fB[4][2];
#pragma unroll
            for (int j = 0; j < 2; j++) {
                uint32_t off = (uint32_t)(((wc * 32 + j * 16 + b_lr) * LDS_A
                                           + ks + b_kc) * 2);
                uint32_t r[4];
                ldm_x4(r, sBh + off);
                fB[j * 2 + 0][0] = r[0]; fB[j * 2 + 0][1] = r[1];
                fB[j * 2 + 1][0] = r[2]; fB[j * 2 + 1][1] = r[3];
            }
#pragma unroll
            for (int mt = 0; mt < 4; mt++)
#pragma unroll
                for (int nt = 0; nt < 4; nt++) {
                    mma16816(acc[mt][nt], fAh[mt], fB[nt]);
                    mma16816(acc[mt][nt], fAl[mt], fB[nt]);
                }
        }
    };

    load_stage(0, 0);
    cpa_commit();
    load_stage(1, KC);
    cpa_commit();
#pragma unroll
    for (int c = 0; c < 8; c++) {
        if (c < 7) cpa_wait<1>(); else cpa_wait<0>();
        __syncthreads();
        if (c < 6) {
            load_stage((c + 2) % NSTAGE, (c + 2) * KC);
            cpa_commit();
        }
        compute_stage(c % NSTAGE);
    }

    // epilogue: fp16 output
#pragma unroll
    for (int mt = 0; mt < 4; mt++) {
        int grow0 = bm + wr * 64 + mt * 16 + qp;
        int grow1 = grow0 + 8;
        int row0, row1;
        bool v0, v1;
        if (lbl) {
            row0 = __ldg(&rowmap[grow0]);
            row1 = __ldg(&rowmap[grow1]);
            v0 = true; v1 = true;
        } else {
            row0 = grow0; row1 = grow1;
            v0 = (grow0 < NNODES) && (__ldg(&flag[grow0]) == 0);
            v1 = (grow1 < NNODES) && (__ldg(&flag[grow1]) == 0);
        }
#pragma unroll
        for (int nt = 0; nt < 4; nt++) {
            int col = bn + wc * 32 + nt * 8 + qr * 2;
            float b0 = __ldg(&bias[col]);
            float b1 = __ldg(&bias[col + 1]);
            if (v0) {
                __half2 o = __floats2half2_rn(acc[mt][nt][0] + b0, acc[mt][nt][1] + b1);
                *(__half2*)(C + (size_t)row0 * HID + col) = o;
            }
            if (v1) {
                __half2 o = __floats2half2_rn(acc[mt][nt][2] + b0, acc[mt][nt][3] + b1);
                *(__half2*)(C + (size_t)row1 * HID + col) = o;
            }
        }
    }
}

// ---------------- fp32 -> fp16 hi/lo pair (initial x only) ----------------
__global__ void to_pair(const float* __restrict__ in,
                        __half* __restrict__ hi, __half* __restrict__ lo, int n4)
{
    int t = blockIdx.x * blockDim.x + threadIdx.x;
    if (t >= n4) return;
    float4 v = ((const float4*)in)[t];
    float vv[4] = {v.x, v.y, v.z, v.w};
    __half hv[4], lv[4];
#pragma unroll
    for (int j = 0; j < 4; j++) {
        hv[j] = __float2half_rn(vv[j]);
        lv[j] = __float2half_rn(vv[j] - __half2float(hv[j]));
    }
    ((uint2*)hi)[t] = *(uint2*)hv;
    ((uint2*)lo)[t] = *(uint2*)lv;
}

// ---------------- CSR build + flags ----------------
__global__ void set_flag(const int* __restrict__ pos, int* __restrict__ flag)
{
    int t = blockIdx.x * blockDim.x + threadIdx.x;
    if (t < NROWS_LBL) flag[__ldg(&pos[t])] = 1;
}
__global__ void csr_hist(const int* __restrict__ dst, int* __restrict__ cnt)
{
    int t = blockIdx.x * blockDim.x + threadIdx.x;
    if (t < NEDGES) atomicAdd(&cnt[__ldg(&dst[t])], 1);
}
__global__ __launch_bounds__(256)
void scan_blk(const int* __restrict__ cnt, int* __restrict__ off, int* __restrict__ bsum)
{
    __shared__ int sh[256];
    int idx = blockIdx.x * 256 + threadIdx.x;
    int v = (idx < NNODES) ? cnt[idx] : 0;
    sh[threadIdx.x] = v;
    __syncthreads();
#pragma unroll
    for (int d = 1; d < 256; d <<= 1) {
        int t = (threadIdx.x >= d) ? sh[threadIdx.x - d] : 0;
        __syncthreads();
        sh[threadIdx.x] += t;
        __syncthreads();
    }
    if (idx < NNODES) off[idx] = sh[threadIdx.x] - v;
    if (threadIdx.x == 255) bsum[blockIdx.x] = sh[255];
}
__global__ __launch_bounds__(256)
void scan_top(const int* __restrict__ bsum, int* __restrict__ boff)
{
    __shared__ int sh[256];
    int v = (threadIdx.x < SCAN_BLKS) ? bsum[threadIdx.x] : 0;
    sh[threadIdx.x] = v;
    __syncthreads();
#pragma unroll
    for (int d = 1; d < 256; d <<= 1) {
        int t = (threadIdx.x >= d) ? sh[threadIdx.x - d] : 0;
        __syncthreads();
        sh[threadIdx.x] += t;
        __syncthreads();
    }
    if (threadIdx.x < SCAN_BLKS) boff[threadIdx.x] = sh[threadIdx.x] - v;
}
__global__ void scan_add(int* __restrict__ off, const int* __restrict__ boff,
                         int* __restrict__ cnt)
{
    int idx = blockIdx.x * 256 + threadIdx.x;
    if (idx < NNODES) {
        off[idx] += boff[blockIdx.x];
        cnt[idx] = 0;
    }
    if (idx == 0) off[NNODES] = NEDGES;
}
__global__ void csr_fill(const int* __restrict__ src, const int* __restrict__ dst,
                         const int* __restrict__ off, int* __restrict__ cur,
                         int* __restrict__ eid)
{
    int t = blockIdx.x * blockDim.x + threadIdx.x;
    if (t >= NEDGES) return;
    int d = __ldg(&dst[t]);
    int p = atomicAdd(&cur[d], 1);
    eid[__ldg(&off[d]) + p] = __ldg(&src[t]);
}

// ---------------- fp16 row accumulate helper ----------------
__device__ __forceinline__ void acc_row(float* a, const __half* h, int e, int lane)
{
    uint4 q = __ldg(&((const uint4*)(h + (size_t)e * HID))[lane]);
    const __half2* hp = (const __half2*)&q;
#pragma unroll
    for (int j = 0; j < 4; j++) {
        float2 f = __half22float2(hp[j]);
        a[j * 2 + 0] += f.x;
        a[j * 2 + 1] += f.y;
    }
}

// ---------------- pull segment-sum: fp16-pair out (layers 0,1) ----------------
__global__ __launch_bounds__(256)
void pull_pair(const __half* __restrict__ h, const int* __restrict__ off,
               const int* __restrict__ eid,
               __half* __restrict__ xh, __half* __restrict__ xl)
{
    int node = blockIdx.x * 8 + (threadIdx.x >> 5);
    if (node >= NNODES) return;
    int lane = threadIdx.x & 31;
    int s0 = __ldg(&off[node]);
    int s1 = __ldg(&off[node + 1]);
    float a[8] = {0.f, 0.f, 0.f, 0.f, 0.f, 0.f, 0.f, 0.f};
    int i = s0;
    for (; i + 1 < s1; i += 2) {
        int e0 = __ldg(&eid[i]);
        int e1 = __ldg(&eid[i + 1]);
        acc_row(a, h, e0, lane);
        acc_row(a, h, e1, lane);
    }
    if (i < s1) acc_row(a, h, __ldg(&eid[i]), lane);

    __half hv[8], lv[8];
#pragma unroll
    for (int j = 0; j < 8; j++) {
        hv[j] = __float2half_rn(a[j]);
        lv[j] = __float2half_rn(a[j] - __half2float(hv[j]));
    }
    *(uint4*)(xh + (size_t)node * HID + lane * 8) = *(uint4*)hv;
    *(uint4*)(xl + (size_t)node * HID + lane * 8) = *(uint4*)lv;
}

// ---------------- last-layer pull: only pos rows, straight to d_out ----------------
__global__ __launch_bounds__(256)
void pull_out(const __half* __restrict__ h, const int* __restrict__ off,
              const int* __restrict__ eid, const int* __restrict__ pos,
              float* __restrict__ out)
{
    int slot = blockIdx.x * 8 + (threadIdx.x >> 5);
    if (slot >= NROWS_LBL) return;
    int lane = threadIdx.x & 31;
    int node = __ldg(&pos[slot]);
    int s0 = __ldg(&off[node]);
    int s1 = __ldg(&off[node + 1]);
    float a[8] = {0.f, 0.f, 0.f, 0.f, 0.f, 0.f, 0.f, 0.f};
    int i = s0;
    for (; i + 1 < s1; i += 2) {
        int e0 = __ldg(&eid[i]);
        int e1 = __ldg(&eid[i + 1]);
        acc_row(a, h, e0, lane);
        acc_row(a, h, e1, lane);
    }
    if (i < s1) acc_row(a, h, __ldg(&eid[i]), lane);

    float4* O = (float4*)out + (size_t)slot * 64 + lane * 2;
    O[0] = make_float4(a[0], a[1], a[2], a[3]);
    O[1] = make_float4(a[4], a[5], a[6], a[7]);
}

// ---------------- launch ----------------
extern "C" void kernel_launch(void* const* d_in, const int* in_sizes, int n_in,
                              void* d_out, int out_size)
{
    (void)in_sizes; (void)n_in; (void)out_size;
    const float* x    = (const float*)d_in[0];
    const float* f0w  = (const float*)d_in[1];
    const float* f0b  = (const float*)d_in[2];
    const float* f1w  = (const float*)d_in[3];
    const float* f1b  = (const float*)d_in[4];
    const float* cw   = (const float*)d_in[5];
    const float* cb   = (const float*)d_in[6];
    const int*   esrc = (const int*)d_in[7];
    const int*   edst = (const int*)d_in[8];
    const int*   pos  = (const int*)d_in[9];

    float *beff;
    __half *h, *xh, *xl, *wt;
    int *cnt, *flag, *off, *eid, *bsum, *boff;
    cudaGetSymbolAddress((void**)&h,    g_h);
    cudaGetSymbolAddress((void**)&xh,   g_xh);
    cudaGetSymbolAddress((void**)&xl,   g_xl);
    cudaGetSymbolAddress((void**)&wt,   g_wt);
    cudaGetSymbolAddress((void**)&beff, g_beff);
    cudaGetSymbolAddress((void**)&cnt,  g_cnt);
    cudaGetSymbolAddress((void**)&flag, g_flag);
    cudaGetSymbolAddress((void**)&off,  g_off);
    cudaGetSymbolAddress((void**)&eid,  g_eid);
    cudaGetSymbolAddress((void**)&bsum, g_bsum);
    cudaGetSymbolAddress((void**)&boff, g_boff);

    const int SMEM_DYN = NSTAGE * STAGE_B;   // 92160
    cudaFuncSetAttribute(tc_gemm, cudaFuncAttributeMaxDynamicSharedMemorySize, SMEM_DYN);

    const int n4 = NNODES * HID / 4;
    dim3 gMerged(GN_BLKS + GL_BLKS, 2);

    fuse_w<<<dim3(32, 6), 256>>>(f0w, f1w, cw, wt);
    fuse_b<<<6, 256>>>(f0b, f1b, cw, cb, beff);
    cudaMemsetAsync(cnt,  0, NNODES * sizeof(int));
    cudaMemsetAsync(flag, 0, NNODES * sizeof(int));
    set_flag<<<(NROWS_LBL + 255) / 256, 256>>>(pos, flag);
    csr_hist<<<(NEDGES + 255) / 256, 256>>>(edst, cnt);
    scan_blk<<<SCAN_BLKS, 256>>>(cnt, off, bsum);
    scan_top<<<1, 256>>>(bsum, boff);
    scan_add<<<SCAN_BLKS, 256>>>(off, boff, cnt);
    csr_fill<<<(NEDGES + 255) / 256, 256>>>(esrc, edst, off, cnt, eid);

    to_pair<<<(n4 + 255) / 256, 256>>>(x, xh, xl, n4);

    for (int i = 0; i < 3; i++) {
        const size_t wo0 = (size_t)(i * 2 + 0) * 65536;
        const size_t wo1 = (size_t)(i * 2 + 1) * 65536;
        tc_gemm<<<gMerged, 256, SMEM_DYN>>>(xh, xl,
                                            wt + wo0, wt + wo1,
                                            beff + (i * 2 + 0) * 256,
                                            beff + (i * 2 + 1) * 256,
                                            h, pos, flag);
        if (i < 2)
            pull_pair<<<(NNODES + 7) / 8, 256>>>(h, off, eid, xh, xl);
        else
            pull_out<<<(NROWS_LBL + 7) / 8, 256>>>(h, off, eid, pos, (float*)d_out);
    }
}

// round 13
// speedup vs baseline: 2.1779x; 1.2474x over previous
#include <cuda_runtime.h>
#include <cuda_fp16.h>
#include <cstdint>
#include <cstddef>

#define HID        256
#define NNODES     50000
#define NEDGES     800000
#define NROWS_LBL  8192
#define SCAN_BLKS  196
#define GN_BLKS    391              // ceil(50000/128)
#define GL_BLKS    64               // 8192/128

// ---------------- scratch ----------------
__device__ __half g_h [(size_t)NNODES * HID];   // conv output, fp16
__device__ __half g_x16[(size_t)NNODES * HID];  // activations, fp16
__device__ __half g_wt[6 * 65536];              // fused W^T [n][k], fp16
__device__ float g_beff[6 * 256];
__device__ int g_cnt[NNODES];
__device__ int g_flag[NNODES];
__device__ int g_off[NNODES + 1];
__device__ int g_eid[NEDGES];
__device__ int g_bsum[SCAN_BLKS];
__device__ int g_boff[SCAN_BLKS];

// ---------------- fused weight precompute ----------------
__global__ __launch_bounds__(256)
void fuse_w(const float* __restrict__ f0w, const float* __restrict__ f1w,
            const float* __restrict__ cw, __half* __restrict__ wt)
{
    __shared__ float sA[8][256];
    const int m = blockIdx.y;
    const int layer = m >> 1, which = m & 1;
    const float* A  = (which == 0 ? f0w : f1w) + (size_t)layer * 65536;
    const float* Wc = cw + (size_t)layer * 65536;
    const int k0 = blockIdx.x * 8;
    const int n  = threadIdx.x;

#pragma unroll
    for (int j = 0; j < 8; j++)
        sA[j][n] = A[(k0 + j) * 256 + n];
    __syncthreads();

    float acc[8];
#pragma unroll
    for (int j = 0; j < 8; j++) acc[j] = 0.f;

    for (int t = 0; t < 256; t++) {
        float wv = __ldg(&Wc[t * 256 + n]);
#pragma unroll
        for (int j = 0; j < 8; j++)
            acc[j] = fmaf(sA[j][t], wv, acc[j]);
    }
#pragma unroll
    for (int j = 0; j < 8; j++)
        wt[(size_t)m * 65536 + n * 256 + k0 + j] = __float2half_rn(acc[j]);
}

__global__ __launch_bounds__(256)
void fuse_b(const float* __restrict__ f0b, const float* __restrict__ f1b,
            const float* __restrict__ cw, const float* __restrict__ cb,
            float* __restrict__ beff)
{
    __shared__ float sB[256];
    const int m = blockIdx.x;
    const int layer = m >> 1, which = m & 1;
    const float* b  = (which == 0 ? f0b : f1b) + (size_t)layer * 256;
    const float* Wc = cw + (size_t)layer * 65536;
    const int n = threadIdx.x;
    sB[n] = b[n];
    __syncthreads();
    float acc = __ldg(&cb[layer * 256 + n]);
#pragma unroll 8
    for (int t = 0; t < 256; t++)
        acc = fmaf(sB[t], __ldg(&Wc[t * 256 + n]), acc);
    beff[m * 256 + n] = acc;
}

// ---------------- mma.sync fp16 GEMM, single pass, 3-stage pipeline ----------------
#define KC      32
#define LDS_A   40
#define TILE_HB (128 * LDS_A * 2)   // 10240 B
#define STAGE_B (2 * TILE_HB)       // A + W = 20480 B
#define NSTAGE  3

__device__ __forceinline__ void mma16816(float* c, const uint32_t* a, const uint32_t* b)
{
    asm volatile(
        "mma.sync.aligned.m16n8k16.row.col.f32.f16.f16.f32 "
        "{%0,%1,%2,%3}, {%4,%5,%6,%7}, {%8,%9}, {%0,%1,%2,%3};"
        : "+f"(c[0]), "+f"(c[1]), "+f"(c[2]), "+f"(c[3])
        : "r"(a[0]), "r"(a[1]), "r"(a[2]), "r"(a[3]), "r"(b[0]), "r"(b[1]));
}
__device__ __forceinline__ void ldm_x4(uint32_t* r, uint32_t addr)
{
    asm volatile("ldmatrix.sync.aligned.m8n8.x4.shared.b16 {%0,%1,%2,%3}, [%4];"
                 : "=r"(r[0]), "=r"(r[1]), "=r"(r[2]), "=r"(r[3]) : "r"(addr));
}
__device__ __forceinline__ void cpa16(uint32_t dst, const void* src, int sz)
{
    asm volatile("cp.async.ca.shared.global [%0], [%1], 16, %2;"
                 :: "r"(dst), "l"(src), "r"(sz));
}
__device__ __forceinline__ void cpa_commit() { asm volatile("cp.async.commit_group;"); }
template <int N>
__device__ __forceinline__ void cpa_wait() {
    asm volatile("cp.async.wait_group %0;" :: "n"(N));
}

// grid.x = GN_BLKS + GL_BLKS (normal tiles, then labeled tiles).
__global__ __launch_bounds__(256, 2)
void tc_gemm(const __half* __restrict__ A,
             const __half* __restrict__ Wt0, const __half* __restrict__ Wt1,
             const float* __restrict__ bias0, const float* __restrict__ bias1,
             __half* __restrict__ C,
             const int* __restrict__ pos, const int* __restrict__ flag)
{
    extern __shared__ __align__(16) char smem_dyn[];

    const bool lbl = (blockIdx.x >= GN_BLKS);
    const __half* Wt  = lbl ? Wt1 : Wt0;
    const float* bias = lbl ? bias1 : bias0;
    const int* rowmap = lbl ? pos : nullptr;
    const int bm = (lbl ? (blockIdx.x - GN_BLKS) : blockIdx.x) * 128;

    const int tid  = threadIdx.x;
    const int wid  = tid >> 5;
    const int lane = tid & 31;
    const int bn   = blockIdx.y * 128;
    const int wr   = wid & 1;
    const int wc   = wid >> 1;
    const int qp = lane >> 2;
    const int qr = lane & 3;

    const uint32_t smem_u = (uint32_t)__cvta_generic_to_shared(smem_dyn);

    const int a_lr = (lane & 7) + ((lane >> 3) & 1) * 8;
    const int a_kc = ((lane >> 4) & 1) * 8;
    const int b_lr = (lane & 7) + ((lane >> 4) & 1) * 8;
    const int b_kc = ((lane >> 3) & 1) * 8;

    float acc[4][4][4];
#pragma unroll
    for (int i = 0; i < 4; i++)
#pragma unroll
        for (int j = 0; j < 4; j++)
#pragma unroll
            for (int r = 0; r < 4; r++) acc[i][j][r] = 0.f;

    int arow[2];
#pragma unroll
    for (int i = 0; i < 2; i++) {
        int u = i * 256 + tid;
        int r = u >> 2;
        int grow = bm + r;
        arow[i] = rowmap ? __ldg(&rowmap[grow]) : (grow < NNODES ? grow : -1);
    }

    auto load_stage = [&](int st, int k0) {
        const uint32_t sb = smem_u + st * STAGE_B;
#pragma unroll
        for (int i = 0; i < 2; i++) {
            int u = i * 256 + tid;
            int r = u >> 2;
            int cq = (u & 3);
            uint32_t doff = (uint32_t)(r * (LDS_A * 2) + cq * 16);
            int khalf = k0 + cq * 8;
            int sz = (arow[i] >= 0) ? 16 : 0;
            const __half* ga = A + ((size_t)(arow[i] >= 0 ? arow[i] : 0)) * HID + khalf;
            cpa16(sb + doff, ga, sz);
            cpa16(sb + TILE_HB + doff, Wt + (size_t)(bn + r) * HID + khalf, 16);
        }
    };

    auto compute_stage = [&](int st) {
        const uint32_t sA = smem_u + st * STAGE_B;
        const uint32_t sB = smem_u + st * STAGE_B + TILE_HB;
#pragma unroll
        for (int ks = 0; ks < KC; ks += 16) {
            uint32_t fA[4][4];
#pragma unroll
            for (int mt = 0; mt < 4; mt++) {
                uint32_t off = (uint32_t)(((wr * 64 + mt * 16 + a_lr) * LDS_A
                                           + ks + a_kc) * 2);
                ldm_x4(fA[mt], sA + off);
            }
            uint32_t fB[4][2];
#pragma unroll
            for (int j = 0; j < 2; j++) {
                uint32_t off = (uint32_t)(((wc * 32 + j * 16 + b_lr) * LDS_A
                                           + ks + b_kc) * 2);
                uint32_t r[4];
                ldm_x4(r, sB + off);
                fB[j * 2 + 0][0] = r[0]; fB[j * 2 + 0][1] = r[1];
                fB[j * 2 + 1][0] = r[2]; fB[j * 2 + 1][1] = r[3];
            }
#pragma unroll
            for (int mt = 0; mt < 4; mt++)
#pragma unroll
                for (int nt = 0; nt < 4; nt++)
                    mma16816(acc[mt][nt], fA[mt], fB[nt]);
        }
    };

    load_stage(0, 0);
    cpa_commit();
    load_stage(1, KC);
    cpa_commit();
#pragma unroll
    for (int c = 0; c < 8; c++) {
        if (c < 7) cpa_wait<1>(); else cpa_wait<0>();
        __syncthreads();
        if (c < 6) {
            load_stage((c + 2) % NSTAGE, (c + 2) * KC);
            cpa_commit();
        }
        compute_stage(c % NSTAGE);
    }

    // epilogue: fp16 output
#pragma unroll
    for (int mt = 0; mt < 4; mt++) {
        int grow0 = bm + wr * 64 + mt * 16 + qp;
        int grow1 = grow0 + 8;
        int row0, row1;
        bool v0, v1;
        if (lbl) {
            row0 = __ldg(&rowmap[grow0]);
            row1 = __ldg(&rowmap[grow1]);
            v0 = true; v1 = true;
        } else {
            row0 = grow0; row1 = grow1;
            v0 = (grow0 < NNODES) && (__ldg(&flag[grow0]) == 0);
            v1 = (grow1 < NNODES) && (__ldg(&flag[grow1]) == 0);
        }
#pragma unroll
        for (int nt = 0; nt < 4; nt++) {
            int col = bn + wc * 32 + nt * 8 + qr * 2;
            float b0 = __ldg(&bias[col]);
            float b1 = __ldg(&bias[col + 1]);
            if (v0) {
                __half2 o = __floats2half2_rn(acc[mt][nt][0] + b0, acc[mt][nt][1] + b1);
                *(__half2*)(C + (size_t)row0 * HID + col) = o;
            }
            if (v1) {
                __half2 o = __floats2half2_rn(acc[mt][nt][2] + b0, acc[mt][nt][3] + b1);
                *(__half2*)(C + (size_t)row1 * HID + col) = o;
            }
        }
    }
}

// ---------------- fp32 -> fp16 (initial x only) ----------------
__global__ void to_half(const float* __restrict__ in, __half* __restrict__ out, int n4)
{
    int t = blockIdx.x * blockDim.x + threadIdx.x;
    if (t >= n4) return;
    float4 v = ((const float4*)in)[t];
    __half2 h0 = __floats2half2_rn(v.x, v.y);
    __half2 h1 = __floats2half2_rn(v.z, v.w);
    uint2 o;
    o.x = *(uint32_t*)&h0;
    o.y = *(uint32_t*)&h1;
    ((uint2*)out)[t] = o;
}

// ---------------- CSR build + flags ----------------
__global__ void set_flag(const int* __restrict__ pos, int* __restrict__ flag)
{
    int t = blockIdx.x * blockDim.x + threadIdx.x;
    if (t < NROWS_LBL) flag[__ldg(&pos[t])] = 1;
}
__global__ void csr_hist(const int* __restrict__ dst, int* __restrict__ cnt)
{
    int t = blockIdx.x * blockDim.x + threadIdx.x;
    if (t < NEDGES) atomicAdd(&cnt[__ldg(&dst[t])], 1);
}
__global__ __launch_bounds__(256)
void scan_blk(const int* __restrict__ cnt, int* __restrict__ off, int* __restrict__ bsum)
{
    __shared__ int sh[256];
    int idx = blockIdx.x * 256 + threadIdx.x;
    int v = (idx < NNODES) ? cnt[idx] : 0;
    sh[threadIdx.x] = v;
    __syncthreads();
#pragma unroll
    for (int d = 1; d < 256; d <<= 1) {
        int t = (threadIdx.x >= d) ? sh[threadIdx.x - d] : 0;
        __syncthreads();
        sh[threadIdx.x] += t;
        __syncthreads();
    }
    if (idx < NNODES) off[idx] = sh[threadIdx.x] - v;
    if (threadIdx.x == 255) bsum[blockIdx.x] = sh[255];
}
__global__ __launch_bounds__(256)
void scan_top(const int* __restrict__ bsum, int* __restrict__ boff)
{
    __shared__ int sh[256];
    int v = (threadIdx.x < SCAN_BLKS) ? bsum[threadIdx.x] : 0;
    sh[threadIdx.x] = v;
    __syncthreads();
#pragma unroll
    for (int d = 1; d < 256; d <<= 1) {
        int t = (threadIdx.x >= d) ? sh[threadIdx.x - d] : 0;
        __syncthreads();
        sh[threadIdx.x] += t;
        __syncthreads();
    }
    if (threadIdx.x < SCAN_BLKS) boff[threadIdx.x] = sh[threadIdx.x] - v;
}
__global__ void scan_add(int* __restrict__ off, const int* __restrict__ boff,
                         int* __restrict__ cnt)
{
    int idx = blockIdx.x * 256 + threadIdx.x;
    if (idx < NNODES) {
        off[idx] += boff[blockIdx.x];
        cnt[idx] = 0;
    }
    if (idx == 0) off[NNODES] = NEDGES;
}
__global__ void csr_fill(const int* __restrict__ src, const int* __restrict__ dst,
                         const int* __restrict__ off, int* __restrict__ cur,
                         int* __restrict__ eid)
{
    int t = blockIdx.x * blockDim.x + threadIdx.x;
    if (t >= NEDGES) return;
    int d = __ldg(&dst[t]);
    int p = atomicAdd(&cur[d], 1);
    eid[__ldg(&off[d]) + p] = __ldg(&src[t]);
}

// ---------------- fp16 row accumulate helper ----------------
__device__ __forceinline__ void acc_row(float* a, const __half* h, int e, int lane)
{
    uint4 q = __ldg(&((const uint4*)(h + (size_t)e * HID))[lane]);
    const __half2* hp = (const __half2*)&q;
#pragma unroll
    for (int j = 0; j < 4; j++) {
        float2 f = __half22float2(hp[j]);
        a[j * 2 + 0] += f.x;
        a[j * 2 + 1] += f.y;
    }
}

// ---------------- pull segment-sum: fp16 out (layers 0,1) ----------------
__global__ __launch_bounds__(256)
void pull_half(const __half* __restrict__ h, const int* __restrict__ off,
               const int* __restrict__ eid, __half* __restrict__ xo)
{
    int node = blockIdx.x * 8 + (threadIdx.x >> 5);
    if (node >= NNODES) return;
    int lane = threadIdx.x & 31;
    int s0 = __ldg(&off[node]);
    int s1 = __ldg(&off[node + 1]);
    float a[8] = {0.f, 0.f, 0.f, 0.f, 0.f, 0.f, 0.f, 0.f};
    int i = s0;
    for (; i + 1 < s1; i += 2) {
        int e0 = __ldg(&eid[i]);
        int e1 = __ldg(&eid[i + 1]);
        acc_row(a, h, e0, lane);
        acc_row(a, h, e1, lane);
    }
    if (i < s1) acc_row(a, h, __ldg(&eid[i]), lane);

    __half hv[8];
#pragma unroll
    for (int j = 0; j < 8; j++) hv[j] = __float2half_rn(a[j]);
    *(uint4*)(xo + (size_t)node * HID + lane * 8) = *(uint4*)hv;
}

// ---------------- last-layer pull: only pos rows, straight to d_out ----------------
__global__ __launch_bounds__(256)
void pull_out(const __half* __restrict__ h, const int* __restrict__ off,
              const int* __restrict__ eid, const int* __restrict__ pos,
              float* __restrict__ out)
{
    int slot = blockIdx.x * 8 + (threadIdx.x >> 5);
    if (slot >= NROWS_LBL) return;
    int lane = threadIdx.x & 31;
    int node = __ldg(&pos[slot]);
    int s0 = __ldg(&off[node]);
    int s1 = __ldg(&off[node + 1]);
    float a[8] = {0.f, 0.f, 0.f, 0.f, 0.f, 0.f, 0.f, 0.f};
    int i = s0;
    for (; i + 1 < s1; i += 2) {
        int e0 = __ldg(&eid[i]);
        int e1 = __ldg(&eid[i + 1]);
        acc_row(a, h, e0, lane);
        acc_row(a, h, e1, lane);
    }
    if (i < s1) acc_row(a, h, __ldg(&eid[i]), lane);

    float4* O = (float4*)out + (size_t)slot * 64 + lane * 2;
    O[0] = make_float4(a[0], a[1], a[2], a[3]);
    O[1] = make_float4(a[4], a[5], a[6], a[7]);
}

// ---------------- launch ----------------
extern "C" void kernel_launch(void* const* d_in, const int* in_sizes, int n_in,
                              void* d_out, int out_size)
{
    (void)in_sizes; (void)n_in; (void)out_size;
    const float* x    = (const float*)d_in[0];
    const float* f0w  = (const float*)d_in[1];
    const float* f0b  = (const float*)d_in[2];
    const float* f1w  = (const float*)d_in[3];
    const float* f1b  = (const float*)d_in[4];
    const float* cw   = (const float*)d_in[5];
    const float* cb   = (const float*)d_in[6];
    const int*   esrc = (const int*)d_in[7];
    const int*   edst = (const int*)d_in[8];
    const int*   pos  = (const int*)d_in[9];

    float *beff;
    __half *h, *x16, *wt;
    int *cnt, *flag, *off, *eid, *bsum, *boff;
    cudaGetSymbolAddress((void**)&h,    g_h);
    cudaGetSymbolAddress((void**)&x16,  g_x16);
    cudaGetSymbolAddress((void**)&wt,   g_wt);
    cudaGetSymbolAddress((void**)&beff, g_beff);
    cudaGetSymbolAddress((void**)&cnt,  g_cnt);
    cudaGetSymbolAddress((void**)&flag, g_flag);
    cudaGetSymbolAddress((void**)&off,  g_off);
    cudaGetSymbolAddress((void**)&eid,  g_eid);
    cudaGetSymbolAddress((void**)&bsum, g_bsum);
    cudaGetSymbolAddress((void**)&boff, g_boff);

    const int SMEM_DYN = NSTAGE * STAGE_B;   // 61440
    cudaFuncSetAttribute(tc_gemm, cudaFuncAttributeMaxDynamicSharedMemorySize, SMEM_DYN);

    const int n4 = NNODES * HID / 4;
    dim3 gMerged(GN_BLKS + GL_BLKS, 2);

    fuse_w<<<dim3(32, 6), 256>>>(f0w, f1w, cw, wt);
    fuse_b<<<6, 256>>>(f0b, f1b, cw, cb, beff);
    cudaMemsetAsync(cnt,  0, NNODES * sizeof(int));
    cudaMemsetAsync(flag, 0, NNODES * sizeof(int));
    set_flag<<<(NROWS_LBL + 255) / 256, 256>>>(pos, flag);
    csr_hist<<<(NEDGES + 255) / 256, 256>>>(edst, cnt);
    scan_blk<<<SCAN_BLKS, 256>>>(cnt, off, bsum);
    scan_top<<<1, 256>>>(bsum, boff);
    scan_add<<<SCAN_BLKS, 256>>>(off, boff, cnt);
    csr_fill<<<(NEDGES + 255) / 256, 256>>>(esrc, edst, off, cnt, eid);

    to_half<<<(n4 + 255) / 256, 256>>>(x, x16, n4);

    for (int i = 0; i < 3; i++) {
        const size_t wo0 = (size_t)(i * 2 + 0) * 65536;
        const size_t wo1 = (size_t)(i * 2 + 1) * 65536;
        tc_gemm<<<gMerged, 256, SMEM_DYN>>>(x16,
                                            wt + wo0, wt + wo1,
                                            beff + (i * 2 + 0) * 256,
                                            beff + (i * 2 + 1) * 256,
                                            h, pos, flag);
        if (i < 2)
            pull_half<<<(NNODES + 7) / 8, 256>>>(h, off, eid, x16);
        else
            pull_out<<<(NROWS_LBL + 7) / 8, 256>>>(h, off, eid, pos, (float*)d_out);
    }
}

// round 14
// speedup vs baseline: 2.2882x; 1.0507x over previous
#include <cuda_runtime.h>
#include <cuda_fp16.h>
#include <cstdint>
#include <cstddef>

#define HID        256
#define NNODES     50000
#define NEDGES     800000
#define NROWS_LBL  8192
#define SCAN_BLKS  196
#define GN_BLKS    391              // ceil(50000/128)
#define GL_BLKS    64               // 8192/128

// ---------------- scratch ----------------
__device__ __half g_h [(size_t)NNODES * HID];   // conv output, fp16
__device__ __half g_x16[(size_t)NNODES * HID];  // activations, fp16
__device__ __half g_wt[6 * 65536];              // fused W^T [n][k], fp16
__device__ float g_beff[6 * 256];
__device__ int g_cnt[NNODES];
__device__ int g_flag[NNODES];
__device__ int g_off[NNODES + 1];
__device__ int g_eid[NEDGES];
__device__ int g_bsum[SCAN_BLKS];
__device__ int g_boff[SCAN_BLKS];

// ---------------- fused weight precompute ----------------
__global__ __launch_bounds__(256)
void fuse_w(const float* __restrict__ f0w, const float* __restrict__ f1w,
            const float* __restrict__ cw, __half* __restrict__ wt)
{
    __shared__ float sA[8][256];
    const int m = blockIdx.y;
    const int layer = m >> 1, which = m & 1;
    const float* A  = (which == 0 ? f0w : f1w) + (size_t)layer * 65536;
    const float* Wc = cw + (size_t)layer * 65536;
    const int k0 = blockIdx.x * 8;
    const int n  = threadIdx.x;

#pragma unroll
    for (int j = 0; j < 8; j++)
        sA[j][n] = A[(k0 + j) * 256 + n];
    __syncthreads();

    float acc[8];
#pragma unroll
    for (int j = 0; j < 8; j++) acc[j] = 0.f;

    for (int t = 0; t < 256; t++) {
        float wv = __ldg(&Wc[t * 256 + n]);
#pragma unroll
        for (int j = 0; j < 8; j++)
            acc[j] = fmaf(sA[j][t], wv, acc[j]);
    }
#pragma unroll
    for (int j = 0; j < 8; j++)
        wt[(size_t)m * 65536 + n * 256 + k0 + j] = __float2half_rn(acc[j]);
}

__global__ __launch_bounds__(256)
void fuse_b(const float* __restrict__ f0b, const float* __restrict__ f1b,
            const float* __restrict__ cw, const float* __restrict__ cb,
            float* __restrict__ beff)
{
    __shared__ float sB[256];
    const int m = blockIdx.x;
    const int layer = m >> 1, which = m & 1;
    const float* b  = (which == 0 ? f0b : f1b) + (size_t)layer * 256;
    const float* Wc = cw + (size_t)layer * 65536;
    const int n = threadIdx.x;
    sB[n] = b[n];
    __syncthreads();
    float acc = __ldg(&cb[layer * 256 + n]);
#pragma unroll 8
    for (int t = 0; t < 256; t++)
        acc = fmaf(sB[t], __ldg(&Wc[t * 256 + n]), acc);
    beff[m * 256 + n] = acc;
}

// ---------------- mma.sync fp16 GEMM, single pass, 3-stage pipeline ----------------
#define KC      32
#define LDS_A   40
#define TILE_HB (128 * LDS_A * 2)   // 10240 B
#define STAGE_B (2 * TILE_HB)       // A + W = 20480 B
#define NSTAGE  3

__device__ __forceinline__ void mma16816(float* c, const uint32_t* a, const uint32_t* b)
{
    asm volatile(
        "mma.sync.aligned.m16n8k16.row.col.f32.f16.f16.f32 "
        "{%0,%1,%2,%3}, {%4,%5,%6,%7}, {%8,%9}, {%0,%1,%2,%3};"
        : "+f"(c[0]), "+f"(c[1]), "+f"(c[2]), "+f"(c[3])
        : "r"(a[0]), "r"(a[1]), "r"(a[2]), "r"(a[3]), "r"(b[0]), "r"(b[1]));
}
__device__ __forceinline__ void ldm_x4(uint32_t* r, uint32_t addr)
{
    asm volatile("ldmatrix.sync.aligned.m8n8.x4.shared.b16 {%0,%1,%2,%3}, [%4];"
                 : "=r"(r[0]), "=r"(r[1]), "=r"(r[2]), "=r"(r[3]) : "r"(addr));
}
__device__ __forceinline__ void cpa16(uint32_t dst, const void* src, int sz)
{
    asm volatile("cp.async.ca.shared.global [%0], [%1], 16, %2;"
                 :: "r"(dst), "l"(src), "r"(sz));
}
__device__ __forceinline__ void cpa_commit() { asm volatile("cp.async.commit_group;"); }
template <int N>
__device__ __forceinline__ void cpa_wait() {
    asm volatile("cp.async.wait_group %0;" :: "n"(N));
}

// grid.x = GN_BLKS + GL_BLKS (normal tiles, then labeled tiles).
__global__ __launch_bounds__(256, 2)
void tc_gemm(const __half* __restrict__ A,
             const __half* __restrict__ Wt0, const __half* __restrict__ Wt1,
             const float* __restrict__ bias0, const float* __restrict__ bias1,
             __half* __restrict__ C,
             const int* __restrict__ pos, const int* __restrict__ flag)
{
    extern __shared__ __align__(16) char smem_dyn[];

    const bool lbl = (blockIdx.x >= GN_BLKS);
    const __half* Wt  = lbl ? Wt1 : Wt0;
    const float* bias = lbl ? bias1 : bias0;
    const int* rowmap = lbl ? pos : nullptr;
    const int bm = (lbl ? (blockIdx.x - GN_BLKS) : blockIdx.x) * 128;

    const int tid  = threadIdx.x;
    const int wid  = tid >> 5;
    const int lane = tid & 31;
    const int bn   = blockIdx.y * 128;
    const int wr   = wid & 1;
    const int wc   = wid >> 1;
    const int qp = lane >> 2;
    const int qr = lane & 3;

    const uint32_t smem_u = (uint32_t)__cvta_generic_to_shared(smem_dyn);

    const int a_lr = (lane & 7) + ((lane >> 3) & 1) * 8;
    const int a_kc = ((lane >> 4) & 1) * 8;
    const int b_lr = (lane & 7) + ((lane >> 4) & 1) * 8;
    const int b_kc = ((lane >> 3) & 1) * 8;

    float acc[4][4][4];
#pragma unroll
    for (int i = 0; i < 4; i++)
#pragma unroll
        for (int j = 0; j < 4; j++)
#pragma unroll
            for (int r = 0; r < 4; r++) acc[i][j][r] = 0.f;

    int arow[2];
#pragma unroll
    for (int i = 0; i < 2; i++) {
        int u = i * 256 + tid;
        int r = u >> 2;
        int grow = bm + r;
        arow[i] = rowmap ? __ldg(&rowmap[grow]) : (grow < NNODES ? grow : -1);
    }

    auto load_stage = [&](int st, int k0) {
        const uint32_t sb = smem_u + st * STAGE_B;
#pragma unroll
        for (int i = 0; i < 2; i++) {
            int u = i * 256 + tid;
            int r = u >> 2;
            int cq = (u & 3);
            uint32_t doff = (uint32_t)(r * (LDS_A * 2) + cq * 16);
            int khalf = k0 + cq * 8;
            int sz = (arow[i] >= 0) ? 16 : 0;
            const __half* ga = A + ((size_t)(arow[i] >= 0 ? arow[i] : 0)) * HID + khalf;
            cpa16(sb + doff, ga, sz);
            cpa16(sb + TILE_HB + doff, Wt + (size_t)(bn + r) * HID + khalf, 16);
        }
    };

    auto compute_stage = [&](int st) {
        const uint32_t sA = smem_u + st * STAGE_B;
        const uint32_t sB = smem_u + st * STAGE_B + TILE_HB;
#pragma unroll
        for (int ks = 0; ks < KC; ks += 16) {
            uint32_t fA[4][4];
#pragma unroll
            for (int mt = 0; mt < 4; mt++) {
                uint32_t off = (uint32_t)(((wr * 64 + mt * 16 + a_lr) * LDS_A
                                           + ks + a_kc) * 2);
                ldm_x4(fA[mt], sA + off);
            }
            uint32_t fB[4][2];
#pragma unroll
            for (int j = 0; j < 2; j++) {
                uint32_t off = (uint32_t)(((wc * 32 + j * 16 + b_lr) * LDS_A
                                           + ks + b_kc) * 2);
                uint32_t r[4];
                ldm_x4(r, sB + off);
                fB[j * 2 + 0][0] = r[0]; fB[j * 2 + 0][1] = r[1];
                fB[j * 2 + 1][0] = r[2]; fB[j * 2 + 1][1] = r[3];
            }
#pragma unroll
            for (int mt = 0; mt < 4; mt++)
#pragma unroll
                for (int nt = 0; nt < 4; nt++)
                    mma16816(acc[mt][nt], fA[mt], fB[nt]);
        }
    };

    load_stage(0, 0);
    cpa_commit();
    load_stage(1, KC);
    cpa_commit();
#pragma unroll
    for (int c = 0; c < 8; c++) {
        if (c < 7) cpa_wait<1>(); else cpa_wait<0>();
        __syncthreads();
        if (c < 6) {
            load_stage((c + 2) % NSTAGE, (c + 2) * KC);
            cpa_commit();
        }
        compute_stage(c % NSTAGE);
    }

    // epilogue: fp16 output
#pragma unroll
    for (int mt = 0; mt < 4; mt++) {
        int grow0 = bm + wr * 64 + mt * 16 + qp;
        int grow1 = grow0 + 8;
        int row0, row1;
        bool v0, v1;
        if (lbl) {
            row0 = __ldg(&rowmap[grow0]);
            row1 = __ldg(&rowmap[grow1]);
            v0 = true; v1 = true;
        } else {
            row0 = grow0; row1 = grow1;
            v0 = (grow0 < NNODES) && (__ldg(&flag[grow0]) == 0);
            v1 = (grow1 < NNODES) && (__ldg(&flag[grow1]) == 0);
        }
#pragma unroll
        for (int nt = 0; nt < 4; nt++) {
            int col = bn + wc * 32 + nt * 8 + qr * 2;
            float b0 = __ldg(&bias[col]);
            float b1 = __ldg(&bias[col + 1]);
            if (v0) {
                __half2 o = __floats2half2_rn(acc[mt][nt][0] + b0, acc[mt][nt][1] + b1);
                *(__half2*)(C + (size_t)row0 * HID + col) = o;
            }
            if (v1) {
                __half2 o = __floats2half2_rn(acc[mt][nt][2] + b0, acc[mt][nt][3] + b1);
                *(__half2*)(C + (size_t)row1 * HID + col) = o;
            }
        }
    }
}

// ---------------- fp32 -> fp16 (initial x only) ----------------
__global__ void to_half(const float* __restrict__ in, __half* __restrict__ out, int n4)
{
    int t = blockIdx.x * blockDim.x + threadIdx.x;
    if (t >= n4) return;
    float4 v = ((const float4*)in)[t];
    __half2 h0 = __floats2half2_rn(v.x, v.y);
    __half2 h1 = __floats2half2_rn(v.z, v.w);
    uint2 o;
    o.x = *(uint32_t*)&h0;
    o.y = *(uint32_t*)&h1;
    ((uint2*)out)[t] = o;
}

// ---------------- CSR build + flags ----------------
__global__ void set_flag(const int* __restrict__ pos, int* __restrict__ flag)
{
    int t = blockIdx.x * blockDim.x + threadIdx.x;
    if (t < NROWS_LBL) flag[__ldg(&pos[t])] = 1;
}
__global__ void csr_hist(const int* __restrict__ dst, int* __restrict__ cnt)
{
    int t = blockIdx.x * blockDim.x + threadIdx.x;
    if (t < NEDGES) atomicAdd(&cnt[__ldg(&dst[t])], 1);
}
__global__ __launch_bounds__(256)
void scan_blk(const int* __restrict__ cnt, int* __restrict__ off, int* __restrict__ bsum)
{
    __shared__ int sh[256];
    int idx = blockIdx.x * 256 + threadIdx.x;
    int v = (idx < NNODES) ? cnt[idx] : 0;
    sh[threadIdx.x] = v;
    __syncthreads();
#pragma unroll
    for (int d = 1; d < 256; d <<= 1) {
        int t = (threadIdx.x >= d) ? sh[threadIdx.x - d] : 0;
        __syncthreads();
        sh[threadIdx.x] += t;
        __syncthreads();
    }
    if (idx < NNODES) off[idx] = sh[threadIdx.x] - v;
    if (threadIdx.x == 255) bsum[blockIdx.x] = sh[255];
}
__global__ __launch_bounds__(256)
void scan_top(const int* __restrict__ bsum, int* __restrict__ boff)
{
    __shared__ int sh[256];
    int v = (threadIdx.x < SCAN_BLKS) ? bsum[threadIdx.x] : 0;
    sh[threadIdx.x] = v;
    __syncthreads();
#pragma unroll
    for (int d = 1; d < 256; d <<= 1) {
        int t = (threadIdx.x >= d) ? sh[threadIdx.x - d] : 0;
        __syncthreads();
        sh[threadIdx.x] += t;
        __syncthreads();
    }
    if (threadIdx.x < SCAN_BLKS) boff[threadIdx.x] = sh[threadIdx.x] - v;
}
__global__ void scan_add(int* __restrict__ off, const int* __restrict__ boff,
                         int* __restrict__ cnt)
{
    int idx = blockIdx.x * 256 + threadIdx.x;
    if (idx < NNODES) {
        off[idx] += boff[blockIdx.x];
        cnt[idx] = 0;
    }
    if (idx == 0) off[NNODES] = NEDGES;
}
__global__ void csr_fill(const int* __restrict__ src, const int* __restrict__ dst,
                         const int* __restrict__ off, int* __restrict__ cur,
                         int* __restrict__ eid)
{
    int t = blockIdx.x * blockDim.x + threadIdx.x;
    if (t >= NEDGES) return;
    int d = __ldg(&dst[t]);
    int p = atomicAdd(&cur[d], 1);
    eid[__ldg(&off[d]) + p] = __ldg(&src[t]);
}

// ---------------- fp16 row accumulate helper ----------------
__device__ __forceinline__ void acc_row(float* a, const __half* h, int e, int lane)
{
    uint4 q = __ldg(&((const uint4*)(h + (size_t)e * HID))[lane]);
    const __half2* hp = (const __half2*)&q;
#pragma unroll
    for (int j = 0; j < 4; j++) {
        float2 f = __half22float2(hp[j]);
        a[j * 2 + 0] += f.x;
        a[j * 2 + 1] += f.y;
    }
}

// ---------------- pull segment-sum: fp16 out (layers 0,1) ----------------
__global__ __launch_bounds__(256)
void pull_half(const __half* __restrict__ h, const int* __restrict__ off,
               const int* __restrict__ eid, __half* __restrict__ xo)
{
    int node = blockIdx.x * 8 + (threadIdx.x >> 5);
    if (node >= NNODES) return;
    int lane = threadIdx.x & 31;
    int s0 = __ldg(&off[node]);
    int s1 = __ldg(&off[node + 1]);
    float a[8] = {0.f, 0.f, 0.f, 0.f, 0.f, 0.f, 0.f, 0.f};
    int i = s0;
    for (; i + 1 < s1; i += 2) {
        int e0 = __ldg(&eid[i]);
        int e1 = __ldg(&eid[i + 1]);
        acc_row(a, h, e0, lane);
        acc_row(a, h, e1, lane);
    }
    if (i < s1) acc_row(a, h, __ldg(&eid[i]), lane);

    __half hv[8];
#pragma unroll
    for (int j = 0; j < 8; j++) hv[j] = __float2half_rn(a[j]);
    *(uint4*)(xo + (size_t)node * HID + lane * 8) = *(uint4*)hv;
}

// ---------------- last-layer pull: only pos rows, straight to d_out ----------------
__global__ __launch_bounds__(256)
void pull_out(const __half* __restrict__ h, const int* __restrict__ off,
              const int* __restrict__ eid, const int* __restrict__ pos,
              float* __restrict__ out)
{
    int slot = blockIdx.x * 8 + (threadIdx.x >> 5);
    if (slot >= NROWS_LBL) return;
    int lane = threadIdx.x & 31;
    int node = __ldg(&pos[slot]);
    int s0 = __ldg(&off[node]);
    int s1 = __ldg(&off[node + 1]);
    float a[8] = {0.f, 0.f, 0.f, 0.f, 0.f, 0.f, 0.f, 0.f};
    int i = s0;
    for (; i + 1 < s1; i += 2) {
        int e0 = __ldg(&eid[i]);
        int e1 = __ldg(&eid[i + 1]);
        acc_row(a, h, e0, lane);
        acc_row(a, h, e1, lane);
    }
    if (i < s1) acc_row(a, h, __ldg(&eid[i]), lane);

    float4* O = (float4*)out + (size_t)slot * 64 + lane * 2;
    O[0] = make_float4(a[0], a[1], a[2], a[3]);
    O[1] = make_float4(a[4], a[5], a[6], a[7]);
}

// ---------------- launch ----------------
extern "C" void kernel_launch(void* const* d_in, const int* in_sizes, int n_in,
                              void* d_out, int out_size)
{
    (void)in_sizes; (void)n_in; (void)out_size;
    const float* x    = (const float*)d_in[0];
    const float* f0w  = (const float*)d_in[1];
    const float* f0b  = (const float*)d_in[2];
    const float* f1w  = (const float*)d_in[3];
    const float* f1b  = (const float*)d_in[4];
    const float* cw   = (const float*)d_in[5];
    const float* cb   = (const float*)d_in[6];
    const int*   esrc = (const int*)d_in[7];
    const int*   edst = (const int*)d_in[8];
    const int*   pos  = (const int*)d_in[9];

    float *beff;
    __half *h, *x16, *wt;
    int *cnt, *flag, *off, *eid, *bsum, *boff;
    cudaGetSymbolAddress((void**)&h,    g_h);
    cudaGetSymbolAddress((void**)&x16,  g_x16);
    cudaGetSymbolAddress((void**)&wt,   g_wt);
    cudaGetSymbolAddress((void**)&beff, g_beff);
    cudaGetSymbolAddress((void**)&cnt,  g_cnt);
    cudaGetSymbolAddress((void**)&flag, g_flag);
    cudaGetSymbolAddress((void**)&off,  g_off);
    cudaGetSymbolAddress((void**)&eid,  g_eid);
    cudaGetSymbolAddress((void**)&bsum, g_bsum);
    cudaGetSymbolAddress((void**)&boff, g_boff);

    const int SMEM_DYN = NSTAGE * STAGE_B;   // 61440
    static bool s_init = false;
    static cudaStream_t s1;
    static cudaEvent_t ev_fork, ev_csr;
    if (!s_init) {
        cudaFuncSetAttribute(tc_gemm, cudaFuncAttributeMaxDynamicSharedMemorySize, SMEM_DYN);
        cudaStreamCreateWithFlags(&s1, cudaStreamNonBlocking);
        cudaEventCreateWithFlags(&ev_fork, cudaEventDisableTiming);
        cudaEventCreateWithFlags(&ev_csr,  cudaEventDisableTiming);
        s_init = true;
    }

    const int n4 = NNODES * HID / 4;
    dim3 gMerged(GN_BLKS + GL_BLKS, 2);

    // ---- fork: CSR build on side stream, compute prologue on main stream ----
    cudaEventRecord(ev_fork, 0);
    cudaStreamWaitEvent(s1, ev_fork, 0);

    // side stream: CSR chain (needed only by the first pull)
    cudaMemsetAsync(cnt, 0, NNODES * sizeof(int), s1);
    csr_hist<<<(NEDGES + 255) / 256, 256, 0, s1>>>(edst, cnt);
    scan_blk<<<SCAN_BLKS, 256, 0, s1>>>(cnt, off, bsum);
    scan_top<<<1, 256, 0, s1>>>(bsum, boff);
    scan_add<<<SCAN_BLKS, 256, 0, s1>>>(off, boff, cnt);
    csr_fill<<<(NEDGES + 255) / 256, 256, 0, s1>>>(esrc, edst, off, cnt, eid);
    cudaEventRecord(ev_csr, s1);

    // main stream: weights, flags, activation convert, GEMM layer 0
    fuse_w<<<dim3(32, 6), 256>>>(f0w, f1w, cw, wt);
    fuse_b<<<6, 256>>>(f0b, f1b, cw, cb, beff);
    cudaMemsetAsync(flag, 0, NNODES * sizeof(int));
    set_flag<<<(NROWS_LBL + 255) / 256, 256>>>(pos, flag);
    to_half<<<(n4 + 255) / 256, 256>>>(x, x16, n4);

    for (int i = 0; i < 3; i++) {
        const size_t wo0 = (size_t)(i * 2 + 0) * 65536;
        const size_t wo1 = (size_t)(i * 2 + 1) * 65536;
        tc_gemm<<<gMerged, 256, SMEM_DYN>>>(x16,
                                            wt + wo0, wt + wo1,
                                            beff + (i * 2 + 0) * 256,
                                            beff + (i * 2 + 1) * 256,
                                            h, pos, flag);
        if (i == 0)
            cudaStreamWaitEvent(0, ev_csr, 0);   // join: pulls need the CSR
        if (i < 2)
            pull_half<<<(NNODES + 7) / 8, 256>>>(h, off, eid, x16);
        else
            pull_out<<<(NROWS_LBL + 7) / 8, 256>>>(h, off, eid, pos, (float*)d_out);
    }
}

// round 15
// speedup vs baseline: 2.4154x; 1.0556x over previous
#include <cuda_runtime.h>
#include <cuda_fp16.h>
#include <cstdint>
#include <cstddef>

#define HID        256
#define NNODES     50000
#define NEDGES     800000
#define NROWS_LBL  8192
#define SCAN_BLKS  196
#define GN_BLKS    391              // ceil(50000/128)
#define GL_BLKS    64               // 8192/128

// ---------------- scratch ----------------
__device__ __half g_h [(size_t)NNODES * HID];   // conv output, fp16
__device__ __half g_x16[(size_t)NNODES * HID];  // activations, fp16
__device__ __half g_wt[6 * 65536];              // fused W^T [n][k], fp16
__device__ float g_beff[6 * 256];
__device__ int g_cnt[NNODES];
__device__ int g_flag[NNODES];
__device__ int g_off[NNODES + 1];
__device__ int g_eid[NEDGES];
__device__ int g_bsum[SCAN_BLKS];
__device__ int g_boff[SCAN_BLKS];

// ---------------- fused weight precompute ----------------
__global__ __launch_bounds__(256)
void fuse_w(const float* __restrict__ f0w, const float* __restrict__ f1w,
            const float* __restrict__ cw, __half* __restrict__ wt)
{
    __shared__ float sA[8][256];
    const int m = blockIdx.y;
    const int layer = m >> 1, which = m & 1;
    const float* A  = (which == 0 ? f0w : f1w) + (size_t)layer * 65536;
    const float* Wc = cw + (size_t)layer * 65536;
    const int k0 = blockIdx.x * 8;
    const int n  = threadIdx.x;

#pragma unroll
    for (int j = 0; j < 8; j++)
        sA[j][n] = A[(k0 + j) * 256 + n];
    __syncthreads();

    float acc[8];
#pragma unroll
    for (int j = 0; j < 8; j++) acc[j] = 0.f;

    for (int t = 0; t < 256; t++) {
        float wv = __ldg(&Wc[t * 256 + n]);
#pragma unroll
        for (int j = 0; j < 8; j++)
            acc[j] = fmaf(sA[j][t], wv, acc[j]);
    }
#pragma unroll
    for (int j = 0; j < 8; j++)
        wt[(size_t)m * 65536 + n * 256 + k0 + j] = __float2half_rn(acc[j]);
}

__global__ __launch_bounds__(256)
void fuse_b(const float* __restrict__ f0b, const float* __restrict__ f1b,
            const float* __restrict__ cw, const float* __restrict__ cb,
            float* __restrict__ beff)
{
    __shared__ float sB[256];
    const int m = blockIdx.x;
    const int layer = m >> 1, which = m & 1;
    const float* b  = (which == 0 ? f0b : f1b) + (size_t)layer * 256;
    const float* Wc = cw + (size_t)layer * 65536;
    const int n = threadIdx.x;
    sB[n] = b[n];
    __syncthreads();
    float acc = __ldg(&cb[layer * 256 + n]);
#pragma unroll 8
    for (int t = 0; t < 256; t++)
        acc = fmaf(sB[t], __ldg(&Wc[t * 256 + n]), acc);
    beff[m * 256 + n] = acc;
}

// ---------------- mma.sync fp16 GEMM, single pass, 3-stage pipeline ----------------
#define KC      32
#define LDS_A   40
#define TILE_HB (128 * LDS_A * 2)   // 10240 B
#define STAGE_B (2 * TILE_HB)       // 20480 B
#define NSTAGE  3

__device__ __forceinline__ void mma16816(float* c, const uint32_t* a, const uint32_t* b)
{
    asm volatile(
        "mma.sync.aligned.m16n8k16.row.col.f32.f16.f16.f32 "
        "{%0,%1,%2,%3}, {%4,%5,%6,%7}, {%8,%9}, {%0,%1,%2,%3};"
        : "+f"(c[0]), "+f"(c[1]), "+f"(c[2]), "+f"(c[3])
        : "r"(a[0]), "r"(a[1]), "r"(a[2]), "r"(a[3]), "r"(b[0]), "r"(b[1]));
}
__device__ __forceinline__ void ldm_x4(uint32_t* r, uint32_t addr)
{
    asm volatile("ldmatrix.sync.aligned.m8n8.x4.shared.b16 {%0,%1,%2,%3}, [%4];"
                 : "=r"(r[0]), "=r"(r[1]), "=r"(r[2]), "=r"(r[3]) : "r"(addr));
}
__device__ __forceinline__ void cpa16(uint32_t dst, const void* src, int sz)
{
    asm volatile("cp.async.ca.shared.global [%0], [%1], 16, %2;"
                 :: "r"(dst), "l"(src), "r"(sz));
}
__device__ __forceinline__ void cpa_commit() { asm volatile("cp.async.commit_group;"); }
template <int N>
__device__ __forceinline__ void cpa_wait() {
    asm volatile("cp.async.wait_group %0;" :: "n"(N));
}

// grid.x = GN_BLKS + GL_BLKS (normal tiles, then labeled tiles).
__global__ __launch_bounds__(256, 2)
void tc_gemm(const __half* __restrict__ A,
             const __half* __restrict__ Wt0, const __half* __restrict__ Wt1,
             const float* __restrict__ bias0, const float* __restrict__ bias1,
             __half* __restrict__ C,
             const int* __restrict__ pos, const int* __restrict__ flag)
{
    extern __shared__ __align__(16) char smem_dyn[];

    const bool lbl = (blockIdx.x >= GN_BLKS);
    const __half* Wt  = lbl ? Wt1 : Wt0;
    const float* bias = lbl ? bias1 : bias0;
    const int* rowmap = lbl ? pos : nullptr;
    const int bm = (lbl ? (blockIdx.x - GN_BLKS) : blockIdx.x) * 128;

    const int tid  = threadIdx.x;
    const int wid  = tid >> 5;
    const int lane = tid & 31;
    const int bn   = blockIdx.y * 128;
    const int wr   = wid & 1;
    const int wc   = wid >> 1;
    const int qp = lane >> 2;
    const int qr = lane & 3;

    const uint32_t smem_u = (uint32_t)__cvta_generic_to_shared(smem_dyn);

    const int a_lr = (lane & 7) + ((lane >> 3) & 1) * 8;
    const int a_kc = ((lane >> 4) & 1) * 8;
    const int b_lr = (lane & 7) + ((lane >> 4) & 1) * 8;
    const int b_kc = ((lane >> 3) & 1) * 8;

    float acc[4][4][4];
#pragma unroll
    for (int i = 0; i < 4; i++)
#pragma unroll
        for (int j = 0; j < 4; j++)
#pragma unroll
            for (int r = 0; r < 4; r++) acc[i][j][r] = 0.f;

    int arow[2];
#pragma unroll
    for (int i = 0; i < 2; i++) {
        int u = i * 256 + tid;
        int r = u >> 2;
        int grow = bm + r;
        arow[i] = rowmap ? __ldg(&rowmap[grow]) : (grow < NNODES ? grow : -1);
    }

    auto load_stage = [&](int st, int k0) {
        const uint32_t sb = smem_u + st * STAGE_B;
#pragma unroll
        for (int i = 0; i < 2; i++) {
            int u = i * 256 + tid;
            int r = u >> 2;
            int cq = (u & 3);
            uint32_t doff = (uint32_t)(r * (LDS_A * 2) + cq * 16);
            int khalf = k0 + cq * 8;
            int sz = (arow[i] >= 0) ? 16 : 0;
            const __half* ga = A + ((size_t)(arow[i] >= 0 ? arow[i] : 0)) * HID + khalf;
            cpa16(sb + doff, ga, sz);
            cpa16(sb + TILE_HB + doff, Wt + (size_t)(bn + r) * HID + khalf, 16);
        }
    };

    auto compute_stage = [&](int st) {
        const uint32_t sA = smem_u + st * STAGE_B;
        const uint32_t sB = smem_u + st * STAGE_B + TILE_HB;
#pragma unroll
        for (int ks = 0; ks < KC; ks += 16) {
            uint32_t fA[4][4];
#pragma unroll
            for (int mt = 0; mt < 4; mt++) {
                uint32_t off = (uint32_t)(((wr * 64 + mt * 16 + a_lr) * LDS_A
                                           + ks + a_kc) * 2);
                ldm_x4(fA[mt], sA + off);
            }
            uint32_t fB[4][2];
#pragma unroll
            for (int j = 0; j < 2; j++) {
                uint32_t off = (uint32_t)(((wc * 32 + j * 16 + b_lr) * LDS_A
                                           + ks + b_kc) * 2);
                uint32_t r[4];
                ldm_x4(r, sB + off);
                fB[j * 2 + 0][0] = r[0]; fB[j * 2 + 0][1] = r[1];
                fB[j * 2 + 1][0] = r[2]; fB[j * 2 + 1][1] = r[3];
            }
#pragma unroll
            for (int mt = 0; mt < 4; mt++)
#pragma unroll
                for (int nt = 0; nt < 4; nt++)
                    mma16816(acc[mt][nt], fA[mt], fB[nt]);
        }
    };

    load_stage(0, 0);
    cpa_commit();
    load_stage(1, KC);
    cpa_commit();
#pragma unroll
    for (int c = 0; c < 8; c++) {
        if (c < 7) cpa_wait<1>(); else cpa_wait<0>();
        __syncthreads();
        if (c < 6) {
            load_stage((c + 2) % NSTAGE, (c + 2) * KC);
            cpa_commit();
        }
        compute_stage(c % NSTAGE);
    }

    // epilogue: fp16 output
#pragma unroll
    for (int mt = 0; mt < 4; mt++) {
        int grow0 = bm + wr * 64 + mt * 16 + qp;
        int grow1 = grow0 + 8;
        int row0, row1;
        bool v0, v1;
        if (lbl) {
            row0 = __ldg(&rowmap[grow0]);
            row1 = __ldg(&rowmap[grow1]);
            v0 = true; v1 = true;
        } else {
            row0 = grow0; row1 = grow1;
            v0 = (grow0 < NNODES) && (__ldg(&flag[grow0]) == 0);
            v1 = (grow1 < NNODES) && (__ldg(&flag[grow1]) == 0);
        }
#pragma unroll
        for (int nt = 0; nt < 4; nt++) {
            int col = bn + wc * 32 + nt * 8 + qr * 2;
            float b0 = __ldg(&bias[col]);
            float b1 = __ldg(&bias[col + 1]);
            if (v0) {
                __half2 o = __floats2half2_rn(acc[mt][nt][0] + b0, acc[mt][nt][1] + b1);
                *(__half2*)(C + (size_t)row0 * HID + col) = o;
            }
            if (v1) {
                __half2 o = __floats2half2_rn(acc[mt][nt][2] + b0, acc[mt][nt][3] + b1);
                *(__half2*)(C + (size_t)row1 * HID + col) = o;
            }
        }
    }
}

// ---------------- fp32 -> fp16 (initial x only) ----------------
__global__ void to_half(const float* __restrict__ in, __half* __restrict__ out, int n4)
{
    int t = blockIdx.x * blockDim.x + threadIdx.x;
    if (t >= n4) return;
    float4 v = ((const float4*)in)[t];
    __half2 h0 = __floats2half2_rn(v.x, v.y);
    __half2 h1 = __floats2half2_rn(v.z, v.w);
    uint2 o;
    o.x = *(uint32_t*)&h0;
    o.y = *(uint32_t*)&h1;
    ((uint2*)out)[t] = o;
}

// ---------------- CSR build + flags ----------------
__global__ void set_flag(const int* __restrict__ pos, int* __restrict__ flag)
{
    int t = blockIdx.x * blockDim.x + threadIdx.x;
    if (t < NROWS_LBL) flag[__ldg(&pos[t])] = 1;
}
__global__ void csr_hist(const int* __restrict__ dst, int* __restrict__ cnt)
{
    int t = blockIdx.x * blockDim.x + threadIdx.x;
    if (t < NEDGES) atomicAdd(&cnt[__ldg(&dst[t])], 1);
}
__global__ __launch_bounds__(256)
void scan_blk(const int* __restrict__ cnt, int* __restrict__ off, int* __restrict__ bsum)
{
    __shared__ int sh[256];
    int idx = blockIdx.x * 256 + threadIdx.x;
    int v = (idx < NNODES) ? cnt[idx] : 0;
    sh[threadIdx.x] = v;
    __syncthreads();
#pragma unroll
    for (int d = 1; d < 256; d <<= 1) {
        int t = (threadIdx.x >= d) ? sh[threadIdx.x - d] : 0;
        __syncthreads();
        sh[threadIdx.x] += t;
        __syncthreads();
    }
    if (idx < NNODES) off[idx] = sh[threadIdx.x] - v;
    if (threadIdx.x == 255) bsum[blockIdx.x] = sh[255];
}
__global__ __launch_bounds__(256)
void scan_top(const int* __restrict__ bsum, int* __restrict__ boff)
{
    __shared__ int sh[256];
    int v = (threadIdx.x < SCAN_BLKS) ? bsum[threadIdx.x] : 0;
    sh[threadIdx.x] = v;
    __syncthreads();
#pragma unroll
    for (int d = 1; d < 256; d <<= 1) {
        int t = (threadIdx.x >= d) ? sh[threadIdx.x - d] : 0;
        __syncthreads();
        sh[threadIdx.x] += t;
        __syncthreads();
    }
    if (threadIdx.x < SCAN_BLKS) boff[threadIdx.x] = sh[threadIdx.x] - v;
}
__global__ void scan_add(int* __restrict__ off, const int* __restrict__ boff,
                         int* __restrict__ cnt)
{
    int idx = blockIdx.x * 256 + threadIdx.x;
    if (idx < NNODES) {
        off[idx] += boff[blockIdx.x];
        cnt[idx] = 0;
    }
    if (idx == 0) off[NNODES] = NEDGES;
}
__global__ void csr_fill(const int* __restrict__ src, const int* __restrict__ dst,
                         const int* __restrict__ off, int* __restrict__ cur,
                         int* __restrict__ eid)
{
    int t = blockIdx.x * blockDim.x + threadIdx.x;
    if (t >= NEDGES) return;
    int d = __ldg(&dst[t]);
    int p = atomicAdd(&cur[d], 1);
    eid[__ldg(&off[d]) + p] = __ldg(&src[t]);
}

// ---------------- fp16 row accumulate helper ----------------
__device__ __forceinline__ void acc_row(float* a, const __half* h, int e, int lane)
{
    uint4 q = __ldg(&((const uint4*)(h + (size_t)e * HID))[lane]);
    const __half2* hp = (const __half2*)&q;
#pragma unroll
    for (int j = 0; j < 4; j++) {
        float2 f = __half22float2(hp[j]);
        a[j * 2 + 0] += f.x;
        a[j * 2 + 1] += f.y;
    }
}

// 4-wide edge accumulation loop (more loads in flight)
__device__ __forceinline__ void acc_segment(float* a, const __half* h,
                                            const int* eid, int s0, int s1, int lane)
{
    int i = s0;
    for (; i + 3 < s1; i += 4) {
        int e0 = __ldg(&eid[i]);
        int e1 = __ldg(&eid[i + 1]);
        int e2 = __ldg(&eid[i + 2]);
        int e3 = __ldg(&eid[i + 3]);
        acc_row(a, h, e0, lane);
        acc_row(a, h, e1, lane);
        acc_row(a, h, e2, lane);
        acc_row(a, h, e3, lane);
    }
    for (; i < s1; i++)
        acc_row(a, h, __ldg(&eid[i]), lane);
}

// ---------------- pull segment-sum: fp16 out (layers 0,1) ----------------
__global__ __launch_bounds__(256)
void pull_half(const __half* __restrict__ h, const int* __restrict__ off,
               const int* __restrict__ eid, __half* __restrict__ xo)
{
    int node = blockIdx.x * 8 + (threadIdx.x >> 5);
    if (node >= NNODES) return;
    int lane = threadIdx.x & 31;
    int s0 = __ldg(&off[node]);
    int s1 = __ldg(&off[node + 1]);
    float a[8] = {0.f, 0.f, 0.f, 0.f, 0.f, 0.f, 0.f, 0.f};
    acc_segment(a, h, eid, s0, s1, lane);

    __half hv[8];
#pragma unroll
    for (int j = 0; j < 8; j++) hv[j] = __float2half_rn(a[j]);
    *(uint4*)(xo + (size_t)node * HID + lane * 8) = *(uint4*)hv;
}

// ---------------- last-layer pull: only pos rows, straight to d_out ----------------
__global__ __launch_bounds__(256)
void pull_out(const __half* __restrict__ h, const int* __restrict__ off,
              const int* __restrict__ eid, const int* __restrict__ pos,
              float* __restrict__ out)
{
    int slot = blockIdx.x * 8 + (threadIdx.x >> 5);
    if (slot >= NROWS_LBL) return;
    int lane = threadIdx.x & 31;
    int node = __ldg(&pos[slot]);
    int s0 = __ldg(&off[node]);
    int s1 = __ldg(&off[node + 1]);
    float a[8] = {0.f, 0.f, 0.f, 0.f, 0.f, 0.f, 0.f, 0.f};
    acc_segment(a, h, eid, s0, s1, lane);

    float4* O = (float4*)out + (size_t)slot * 64 + lane * 2;
    O[0] = make_float4(a[0], a[1], a[2], a[3]);
    O[1] = make_float4(a[4], a[5], a[6], a[7]);
}

// ---------------- launch ----------------
extern "C" void kernel_launch(void* const* d_in, const int* in_sizes, int n_in,
                              void* d_out, int out_size)
{
    (void)in_sizes; (void)n_in; (void)out_size;
    const float* x    = (const float*)d_in[0];
    const float* f0w  = (const float*)d_in[1];
    const float* f0b  = (const float*)d_in[2];
    const float* f1w  = (const float*)d_in[3];
    const float* f1b  = (const float*)d_in[4];
    const float* cw   = (const float*)d_in[5];
    const float* cb   = (const float*)d_in[6];
    const int*   esrc = (const int*)d_in[7];
    const int*   edst = (const int*)d_in[8];
    const int*   pos  = (const int*)d_in[9];

    float *beff;
    __half *h, *x16, *wt;
    int *cnt, *flag, *off, *eid, *bsum, *boff;
    cudaGetSymbolAddress((void**)&h,    g_h);
    cudaGetSymbolAddress((void**)&x16,  g_x16);
    cudaGetSymbolAddress((void**)&wt,   g_wt);
    cudaGetSymbolAddress((void**)&beff, g_beff);
    cudaGetSymbolAddress((void**)&cnt,  g_cnt);
    cudaGetSymbolAddress((void**)&flag, g_flag);
    cudaGetSymbolAddress((void**)&off,  g_off);
    cudaGetSymbolAddress((void**)&eid,  g_eid);
    cudaGetSymbolAddress((void**)&bsum, g_bsum);
    cudaGetSymbolAddress((void**)&boff, g_boff);

    const int SMEM_DYN = NSTAGE * STAGE_B;   // 61440
    static bool s_init = false;
    static cudaStream_t s1, s2;
    static cudaEvent_t ev_fork, ev_csr, ev_pre;
    if (!s_init) {
        cudaFuncSetAttribute(tc_gemm, cudaFuncAttributeMaxDynamicSharedMemorySize, SMEM_DYN);
        cudaStreamCreateWithFlags(&s1, cudaStreamNonBlocking);
        cudaStreamCreateWithFlags(&s2, cudaStreamNonBlocking);
        cudaEventCreateWithFlags(&ev_fork, cudaEventDisableTiming);
        cudaEventCreateWithFlags(&ev_csr,  cudaEventDisableTiming);
        cudaEventCreateWithFlags(&ev_pre,  cudaEventDisableTiming);
        s_init = true;
    }

    const int n4 = NNODES * HID / 4;
    dim3 gMerged(GN_BLKS + GL_BLKS, 2);

    // ---- fork ----
    cudaEventRecord(ev_fork, 0);
    cudaStreamWaitEvent(s1, ev_fork, 0);
    cudaStreamWaitEvent(s2, ev_fork, 0);

    // s1: CSR chain (needed by the first pull)
    cudaMemsetAsync(cnt, 0, NNODES * sizeof(int), s1);
    csr_hist<<<(NEDGES + 255) / 256, 256, 0, s1>>>(edst, cnt);
    scan_blk<<<SCAN_BLKS, 256, 0, s1>>>(cnt, off, bsum);
    scan_top<<<1, 256, 0, s1>>>(bsum, boff);
    scan_add<<<SCAN_BLKS, 256, 0, s1>>>(off, boff, cnt);
    csr_fill<<<(NEDGES + 255) / 256, 256, 0, s1>>>(esrc, edst, off, cnt, eid);
    cudaEventRecord(ev_csr, s1);

    // s2: flags + activation convert (needed by GEMM-0)
    cudaMemsetAsync(flag, 0, NNODES * sizeof(int), s2);
    set_flag<<<(NROWS_LBL + 255) / 256, 256, 0, s2>>>(pos, flag);
    to_half<<<(n4 + 255) / 256, 256, 0, s2>>>(x, x16, n4);
    cudaEventRecord(ev_pre, s2);

    // main: fused weights (needed by GEMM-0)
    fuse_w<<<dim3(32, 6), 256>>>(f0w, f1w, cw, wt);
    fuse_b<<<6, 256>>>(f0b, f1b, cw, cb, beff);
    cudaStreamWaitEvent(0, ev_pre, 0);

    for (int i = 0; i < 3; i++) {
        const size_t wo0 = (size_t)(i * 2 + 0) * 65536;
        const size_t wo1 = (size_t)(i * 2 + 1) * 65536;
        tc_gemm<<<gMerged, 256, SMEM_DYN>>>(x16,
                                            wt + wo0, wt + wo1,
                                            beff + (i * 2 + 0) * 256,
                                            beff + (i * 2 + 1) * 256,
                                            h, pos, flag);
        if (i == 0)
            cudaStreamWaitEvent(0, ev_csr, 0);   // join: pulls need the CSR
        if (i < 2)
            pull_half<<<(NNODES + 7) / 8, 256>>>(h, off, eid, x16);
        else
            pull_out<<<(NROWS_LBL + 7) / 8, 256>>>(h, off, eid, pos, (float*)d_out);
    }
}